// round 6
// baseline (speedup 1.0000x reference)
#include <cuda_runtime.h>
#include <cuda_bf16.h>
#include <math.h>
#include <stdint.h>

#define N_TOKENS 16384
#define D_MODEL  512
#define NQ       10
#define NL       2
#define DIM      1024
#define K1       1536   // 3*512
#define K2       3072   // 3*1024

#define BM 128
#define BN 256
#define BKB 128                    // K bytes per stage (64 bf16)
#define NSTAGES 4
#define TILE_A (BM*BKB)            // 16 KB
#define TILE_Bb (BN*BKB)           // 32 KB
#define STAGE_B (TILE_A+TILE_Bb)   // 48 KB
#define SMEM_TOTAL (NSTAGES*STAGE_B)   // 192 KB

__device__ __align__(16) float          g_Ur[DIM*DIM];
__device__ __align__(16) float          g_Ui[DIM*DIM];
__device__ __align__(16) float          g_xq[N_TOKENS*DIM];
__device__ __align__(16) float          g_pre[N_TOKENS*D_MODEL];
__device__ __align__(16) __nv_bfloat16  g_xs[N_TOKENS*K1];
__device__ __align__(16) __nv_bfloat16  g_Wins[DIM*K1];
__device__ __align__(16) __nv_bfloat16  g_psis[N_TOKENS*K2];
__device__ __align__(16) __nv_bfloat16  g_U2[2048*K2];
__device__ __align__(16) __nv_bfloat16  g_P[N_TOKENS*K2];
__device__ __align__(16) __nv_bfloat16  g_Wouts[D_MODEL*K2];

// ---------------- PTX helpers (sm_80-era only; no 'a' features) --------------
__device__ __forceinline__ uint32_t smem_u32(const void* p) {
    return (uint32_t)__cvta_generic_to_shared(p);
}
#define CP16(saddr, gaddr) \
    asm volatile("cp.async.cg.shared.global [%0], [%1], 16;" \
                 :: "r"(saddr), "l"(gaddr) : "memory")
#define CP_COMMIT() asm volatile("cp.async.commit_group;" ::: "memory")
#define CP_WAIT2()  asm volatile("cp.async.wait_group 2;" ::: "memory")

#define LDSM4(r0,r1,r2,r3,addr) \
    asm volatile("ldmatrix.sync.aligned.m8n8.x4.shared.b16 {%0,%1,%2,%3}, [%4];" \
                 : "=r"(r0), "=r"(r1), "=r"(r2), "=r"(r3) : "r"(addr))

#define MMA16816(c, a0,a1,a2,a3, b0,b1) \
    asm volatile("mma.sync.aligned.m16n8k16.row.col.f32.bf16.bf16.f32 " \
                 "{%0,%1,%2,%3}, {%4,%5,%6,%7}, {%8,%9}, {%0,%1,%2,%3};" \
                 : "+f"((c)[0]), "+f"((c)[1]), "+f"((c)[2]), "+f"((c)[3]) \
                 : "r"(a0), "r"(a1), "r"(a2), "r"(a3), "r"(b0), "r"(b1))

#define SW128(off) ((off) ^ (((off) >> 3) & 0x70))

// ---------------- bf16 mma GEMM (128x256 tile, 64x64 warp tile) --------------
// C[M,N] = A[M,Kp] @ B[N,Kp]^T ; A,B bf16 K-major. EPI=0: C fp32 (+bias).
// EPI=1: output cols are (re,im) pairs -> prob = re^2+im^2, split to bf16
//        hi/lo and written to P[M,K2] segments [hi|hi|lo].
template<int EPI>
__global__ __launch_bounds__(256, 1)
void gemm_mma(const __nv_bfloat16* __restrict__ A,
              const __nv_bfloat16* __restrict__ B,
              float* __restrict__ C,
              __nv_bfloat16* __restrict__ P,
              const float* __restrict__ bias,
              int M, int N, int Kp)
{
    extern __shared__ char smem[];
    const uint32_t S0 = smem_u32(smem);
    const int tid  = threadIdx.x;
    const int wid  = tid >> 5;
    const int lane = tid & 31;
    const int warp_m = (wid & 1) * 64;   // 2 warps along M
    const int warp_n = (wid >> 1) * 64;  // 4 warps along N
    const int m0 = blockIdx.y * BM;
    const int n0 = blockIdx.x * BN;
    const int nks = Kp / 64;

    const size_t ldb = (size_t)Kp * 2;
    const size_t Ab = (size_t)__cvta_generic_to_global(A) + (size_t)m0 * ldb;
    const size_t Bb = (size_t)__cvta_generic_to_global(B) + (size_t)n0 * ldb;

    // precomputed per-thread ldsm row offsets (within-tile, before kk column)
    const int a_row = (lane & 15);            // + warp_m + mt*16
    const int a_koff = (lane >> 4) << 4;
    const int b_row = (lane & 7) + ((lane >> 4) << 3);  // + warp_n + nt2*16
    const int b_koff = ((lane >> 3) & 1) << 4;

    float c[4][8][4];
    #pragma unroll
    for (int mt = 0; mt < 4; mt++)
        #pragma unroll
        for (int nt = 0; nt < 8; nt++)
            #pragma unroll
            for (int j = 0; j < 4; j++) c[mt][nt][j] = 0.f;

    #pragma unroll
    for (int s = 0; s < NSTAGES - 1; s++) {
        const uint32_t saA = S0 + s * STAGE_B;
        const uint32_t saB = saA + TILE_A;
        const size_t ka = Ab + (size_t)s * BKB;
        const size_t kb = Bb + (size_t)s * BKB;
        #pragma unroll
        for (int i = 0; i < 12; i++) {
            int cc = tid + 256 * i;
            if (cc < 1024) {
                int r = cc >> 3, p = (cc & 7) * 16;
                CP16(saA + SW128(r*128 + p), ka + (size_t)r * ldb + p);
            } else {
                int c2 = cc - 1024;
                int r = c2 >> 3, p = (c2 & 7) * 16;
                CP16(saB + SW128(r*128 + p), kb + (size_t)r * ldb + p);
            }
        }
        CP_COMMIT();
    }

    uint32_t a[2][4][4], b[2][4][4];   // double-buffered fragments

    for (int ks = 0; ks < nks; ks++) {
        CP_WAIT2();
        __syncthreads();

        const uint32_t saA = S0 + (ks % NSTAGES) * STAGE_B;
        const uint32_t saB = saA + TILE_A;

        // load fragments for kk=0 into buffer 0
        #pragma unroll
        for (int mt = 0; mt < 4; mt++) {
            int r = warp_m + mt*16 + a_row;
            LDSM4(a[0][mt][0], a[0][mt][1], a[0][mt][2], a[0][mt][3],
                  saA + SW128(r*128 + a_koff));
        }
        #pragma unroll
        for (int nt2 = 0; nt2 < 4; nt2++) {
            int r = warp_n + nt2*16 + b_row;
            LDSM4(b[0][nt2][0], b[0][nt2][1], b[0][nt2][2], b[0][nt2][3],
                  saB + SW128(r*128 + b_koff));
        }

        // issue cp.async for stage ks+NSTAGES-1
        int ld = ks + NSTAGES - 1;
        if (ld < nks) {
            int slot = ld % NSTAGES;
            const uint32_t pA = S0 + slot * STAGE_B;
            const uint32_t pB = pA + TILE_A;
            const size_t ka = Ab + (size_t)ld * BKB;
            const size_t kb = Bb + (size_t)ld * BKB;
            #pragma unroll
            for (int i = 0; i < 12; i++) {
                int cc = tid + 256 * i;
                if (cc < 1024) {
                    int r = cc >> 3, p = (cc & 7) * 16;
                    CP16(pA + SW128(r*128 + p), ka + (size_t)r * ldb + p);
                } else {
                    int c2 = cc - 1024;
                    int r = c2 >> 3, p = (c2 & 7) * 16;
                    CP16(pB + SW128(r*128 + p), kb + (size_t)r * ldb + p);
                }
            }
        }
        CP_COMMIT();

        // kk loop: prefetch kk+1 fragments, then MMA on kk
        #pragma unroll
        for (int kk = 0; kk < 4; kk++) {
            const int cur = kk & 1, nxt = cur ^ 1;
            if (kk < 3) {
                #pragma unroll
                for (int mt = 0; mt < 4; mt++) {
                    int r = warp_m + mt*16 + a_row;
                    LDSM4(a[nxt][mt][0], a[nxt][mt][1], a[nxt][mt][2], a[nxt][mt][3],
                          saA + SW128(r*128 + (kk+1)*32 + a_koff));
                }
                #pragma unroll
                for (int nt2 = 0; nt2 < 4; nt2++) {
                    int r = warp_n + nt2*16 + b_row;
                    LDSM4(b[nxt][nt2][0], b[nxt][nt2][1], b[nxt][nt2][2], b[nxt][nt2][3],
                          saB + SW128(r*128 + (kk+1)*32 + b_koff));
                }
            }
            #pragma unroll
            for (int mt = 0; mt < 4; mt++)
                #pragma unroll
                for (int nt = 0; nt < 8; nt++)
                    MMA16816(c[mt][nt],
                             a[cur][mt][0], a[cur][mt][1], a[cur][mt][2], a[cur][mt][3],
                             b[cur][nt >> 1][(nt & 1) * 2],
                             b[cur][nt >> 1][(nt & 1) * 2 + 1]);
        }
    }

    // ---- epilogue ----
    #pragma unroll
    for (int mt = 0; mt < 4; mt++) {
        int r0 = m0 + warp_m + mt*16 + (lane >> 2);
        #pragma unroll
        for (int nt = 0; nt < 8; nt++) {
            if (EPI == 0) {
                int nn = n0 + warp_n + nt*8 + 2*(lane & 3);
                float b0 = bias ? bias[nn] : 0.f;
                float b1 = bias ? bias[nn+1] : 0.f;
                float2 v0 = make_float2(c[mt][nt][0] + b0, c[mt][nt][1] + b1);
                float2 v1 = make_float2(c[mt][nt][2] + b0, c[mt][nt][3] + b1);
                *(float2*)(C + (size_t)r0 * N + nn) = v0;
                *(float2*)(C + (size_t)(r0+8) * N + nn) = v1;
            } else {
                int pcol = ((n0 + warp_n + nt*8) >> 1) + (lane & 3);
                float p0 = c[mt][nt][0]*c[mt][nt][0] + c[mt][nt][1]*c[mt][nt][1];
                float p1 = c[mt][nt][2]*c[mt][nt][2] + c[mt][nt][3]*c[mt][nt][3];
                __nv_bfloat16 h0 = __float2bfloat16(p0);
                __nv_bfloat16 l0 = __float2bfloat16(p0 - __bfloat162float(h0));
                __nv_bfloat16 h1 = __float2bfloat16(p1);
                __nv_bfloat16 l1 = __float2bfloat16(p1 - __bfloat162float(h1));
                __nv_bfloat16* pr0 = P + (size_t)r0 * K2 + pcol;
                __nv_bfloat16* pr1 = P + (size_t)(r0+8) * K2 + pcol;
                pr0[0] = h0; pr0[1024] = h0; pr0[2048] = l0;
                pr1[0] = h1; pr1[1024] = h1; pr1[2048] = l1;
            }
        }
    }
}

// ---------------- circuit unitary ---------------------------------------------
__device__ __forceinline__ float2 cmul(float2 a, float2 b) {
    return make_float2(a.x*b.x - a.y*b.y, a.x*b.y + a.y*b.x);
}
__device__ __forceinline__ float2 cadd(float2 a, float2 b) {
    return make_float2(a.x + b.x, a.y + b.y);
}

__global__ void build_unitary(const float* __restrict__ rot,
                              const float* __restrict__ ent,
                              float* __restrict__ Ur, float* __restrict__ Ui) {
    __shared__ float2 st[DIM];
    const int j = blockIdx.x;
    const int t = threadIdx.x;
    for (int i = t; i < DIM; i += 256)
        st[i] = make_float2(i == j ? 1.f : 0.f, 0.f);
    __syncthreads();
    for (int l = 0; l < NL; l++) {
        for (int q = 0; q < NQ; q++) {
            const float t1 = rot[(l*NQ + q)*3 + 0];
            const float t2 = rot[(l*NQ + q)*3 + 1];
            const float t3 = rot[(l*NQ + q)*3 + 2];
            float c1, s1; sincosf(0.5f*t1, &s1, &c1);
            float2 rx00 = {c1,0.f}, rx01 = {0.f,-s1}, rx10 = {0.f,-s1}, rx11 = {c1,0.f};
            float c2, s2; sincosf(0.5f*t2, &s2, &c2);
            float2 ry00 = {c2,0.f}, ry01 = {-s2,0.f}, ry10 = {s2,0.f}, ry11 = {c2,0.f};
            float2 a00 = cadd(cmul(ry00,rx00), cmul(ry01,rx10));
            float2 a01 = cadd(cmul(ry00,rx01), cmul(ry01,rx11));
            float2 a10 = cadd(cmul(ry10,rx00), cmul(ry11,rx10));
            float2 a11 = cadd(cmul(ry10,rx01), cmul(ry11,rx11));
            float cz, sz; sincosf(0.5f*t3, &sz, &cz);
            float2 ez0 = {cz,-sz}, ez1 = {cz,sz};
            float2 m00 = cmul(ez0,a00), m01 = cmul(ez0,a01);
            float2 m10 = cmul(ez1,a10), m11 = cmul(ez1,a11);
            const int mask = 1 << (NQ - 1 - q);
            for (int p = t; p < DIM/2; p += 256) {
                int i0 = ((p & ~(mask-1)) << 1) | (p & (mask-1));
                int i1 = i0 | mask;
                float2 v0 = st[i0], v1 = st[i1];
                st[i0] = cadd(cmul(m00,v0), cmul(m01,v1));
                st[i1] = cadd(cmul(m10,v0), cmul(m11,v1));
            }
            __syncthreads();
        }
        for (int i = t; i < DIM; i += 256) {
            float ang = 0.f;
            #pragma unroll
            for (int g = 0; g < NQ-1; g++) {
                int b1 = (i >> (NQ-1-g)) & 1;
                int b2 = (i >> (NQ-2-g)) & 1;
                if (b1 & b2) ang += ent[l*(NQ-1) + g];
            }
            float sn, cs; sincosf(ang, &sn, &cs);
            st[i] = cmul(st[i], make_float2(cs, sn));
        }
        __syncthreads();
    }
    for (int i = t; i < DIM; i += 256) {
        Ur[i*DIM + j] = st[i].x;
        Ui[i*DIM + j] = st[i].y;
    }
}

// ---------------- split / pack ------------------------------------------------
__device__ __forceinline__ void split2(float v, __nv_bfloat16& h, __nv_bfloat16& l) {
    h = __float2bfloat16(v);
    l = __float2bfloat16(v - __bfloat162float(h));
}

__global__ void split_x(const float* __restrict__ x, __nv_bfloat16* __restrict__ xs) {
    int i = blockIdx.x * blockDim.x + threadIdx.x;
    if (i >= N_TOKENS * D_MODEL) return;
    int m = i / D_MODEL, k = i % D_MODEL;
    __nv_bfloat16 h, l; split2(x[i], h, l);
    __nv_bfloat16* row = xs + (size_t)m * K1;
    row[k] = h; row[512 + k] = h; row[1024 + k] = l;
}

__global__ void split_Win(const float* __restrict__ W, __nv_bfloat16* __restrict__ Ws) {
    int i = blockIdx.x * blockDim.x + threadIdx.x;
    if (i >= DIM * D_MODEL) return;
    int n = i / D_MODEL, k = i % D_MODEL;
    __nv_bfloat16 h, l; split2(W[i], h, l);
    __nv_bfloat16* row = Ws + (size_t)n * K1;
    row[k] = h; row[512 + k] = l; row[1024 + k] = h;
}

__global__ void split_Wout(const float* __restrict__ W, __nv_bfloat16* __restrict__ Ws) {
    int i = blockIdx.x * blockDim.x + threadIdx.x;
    if (i >= D_MODEL * DIM) return;
    int n = i / DIM, k = i % DIM;
    __nv_bfloat16 h, l; split2(W[i], h, l);
    __nv_bfloat16* row = Ws + (size_t)n * K2;
    row[k] = h; row[1024 + k] = l; row[2048 + k] = h;
}

// U2 rows: 2j = Ur[j,:], 2j+1 = Ui[j,:]; cols [hi|lo|hi]
__global__ void pack_U(const float* __restrict__ Ur, const float* __restrict__ Ui,
                       __nv_bfloat16* __restrict__ U2) {
    int i = blockIdx.x * blockDim.x + threadIdx.x;
    if (i >= 2048 * DIM) return;
    int n = i / DIM, k = i % DIM;
    int j = n >> 1;
    float v = (n & 1) ? Ui[(size_t)j*DIM + k] : Ur[(size_t)j*DIM + k];
    __nv_bfloat16 h, l; split2(v, h, l);
    __nv_bfloat16* row = U2 + (size_t)n * K2;
    row[k] = h; row[1024 + k] = l; row[2048 + k] = h;
}

// ---------------- reductions ----------------------------------------------------
__device__ float blockReduceSum256(float v) {
    __shared__ float sh[8];
    __syncthreads();
    int lane = threadIdx.x & 31, wid = threadIdx.x >> 5;
    #pragma unroll
    for (int o = 16; o > 0; o >>= 1) v += __shfl_down_sync(0xffffffffu, v, o);
    if (lane == 0) sh[wid] = v;
    __syncthreads();
    float s = 0.f;
    if (threadIdx.x < 8) s = sh[threadIdx.x];
    if (wid == 0) {
        #pragma unroll
        for (int o = 4; o > 0; o >>= 1) s += __shfl_down_sync(0xffu, s, o);
        if (lane == 0) sh[0] = s;
    }
    __syncthreads();
    return sh[0];
}

__global__ void rownorm_split(const float* __restrict__ xq,
                              __nv_bfloat16* __restrict__ psis) {
    const int row = blockIdx.x;
    const float* p = xq + (size_t)row * DIM;
    const int t = threadIdx.x;
    float v0 = p[t], v1 = p[t+256], v2 = p[t+512], v3 = p[t+768];
    float ss = blockReduceSum256(v0*v0 + v1*v1 + v2*v2 + v3*v3);
    float sc = 1.f / fmaxf(sqrtf(ss), 1e-12f);
    __nv_bfloat16* out = psis + (size_t)row * K2;
    float vv[4] = {v0*sc, v1*sc, v2*sc, v3*sc};
    #pragma unroll
    for (int i = 0; i < 4; i++) {
        int k = t + i*256;
        __nv_bfloat16 h, l; split2(vv[i], h, l);
        out[k] = h; out[1024 + k] = h; out[2048 + k] = l;
    }
}

__global__ void layernorm(const float* __restrict__ in,
                          const float* __restrict__ w, const float* __restrict__ b,
                          float* __restrict__ out) {
    const int row = blockIdx.x;
    const float* p = in + (size_t)row * D_MODEL;
    const int t = threadIdx.x;
    float v0 = p[t], v1 = p[t+256];
    float mu = blockReduceSum256(v0 + v1) * (1.f / D_MODEL);
    float d0 = v0 - mu, d1 = v1 - mu;
    float var = blockReduceSum256(d0*d0 + d1*d1) * (1.f / D_MODEL);
    float inv = rsqrtf(var + 1e-5f);
    float* o = out + (size_t)row * D_MODEL;
    o[t]     = d0 * inv * w[t]     + b[t];
    o[t+256] = d1 * inv * w[t+256] + b[t+256];
}

// ---------------- launch ---------------------------------------------------------
extern "C" void kernel_launch(void* const* d_in, const int* in_sizes, int n_in,
                              void* d_out, int out_size) {
    const float* x     = (const float*)d_in[0];
    const float* W_in  = (const float*)d_in[1];
    const float* b_in  = (const float*)d_in[2];
    const float* W_out = (const float*)d_in[3];
    const float* b_out = (const float*)d_in[4];
    const float* rot   = (const float*)d_in[5];
    const float* ent   = (const float*)d_in[6];
    const float* ln_w  = (const float*)d_in[7];
    const float* ln_b  = (const float*)d_in[8];
    float* out = (float*)d_out;

    float *Ur, *Ui, *xq, *pre;
    __nv_bfloat16 *xs, *Wins, *psis, *U2, *P, *Wouts;
    cudaGetSymbolAddress((void**)&Ur,    g_Ur);
    cudaGetSymbolAddress((void**)&Ui,    g_Ui);
    cudaGetSymbolAddress((void**)&xq,    g_xq);
    cudaGetSymbolAddress((void**)&pre,   g_pre);
    cudaGetSymbolAddress((void**)&xs,    g_xs);
    cudaGetSymbolAddress((void**)&Wins,  g_Wins);
    cudaGetSymbolAddress((void**)&psis,  g_psis);
    cudaGetSymbolAddress((void**)&U2,    g_U2);
    cudaGetSymbolAddress((void**)&P,     g_P);
    cudaGetSymbolAddress((void**)&Wouts, g_Wouts);

    cudaFuncSetAttribute(gemm_mma<0>, cudaFuncAttributeMaxDynamicSharedMemorySize, SMEM_TOTAL);
    cudaFuncSetAttribute(gemm_mma<1>, cudaFuncAttributeMaxDynamicSharedMemorySize, SMEM_TOTAL);

    build_unitary<<<DIM, 256>>>(rot, ent, Ur, Ui);
    pack_U<<<(2048*DIM + 255)/256, 256>>>(Ur, Ui, U2);
    split_x<<<(N_TOKENS*D_MODEL + 255)/256, 256>>>(x, xs);
    split_Win<<<(DIM*D_MODEL + 255)/256, 256>>>(W_in, Wins);
    split_Wout<<<(D_MODEL*DIM + 255)/256, 256>>>(W_out, Wouts);

    // GEMM1: xq = x @ W_in^T + b_in  (K'=1536)
    gemm_mma<0><<<dim3(DIM/BN, N_TOKENS/BM), 256, SMEM_TOTAL>>>(
        xs, Wins, xq, nullptr, b_in, N_TOKENS, DIM, K1);

    // normalize + split -> psis (K'=3072)
    rownorm_split<<<N_TOKENS, 256>>>(xq, psis);

    // GEMM2: (re,im) interleaved vs U2 (N=2048); epilogue emits P = split probs
    gemm_mma<1><<<dim3(2048/BN, N_TOKENS/BM), 256, SMEM_TOTAL>>>(
        psis, U2, nullptr, P, nullptr, N_TOKENS, 2048, K2);

    // GEMM3: pre = probs @ W_out^T + b_out
    gemm_mma<0><<<dim3(D_MODEL/BN, N_TOKENS/BM), 256, SMEM_TOTAL>>>(
        P, Wouts, pre, nullptr, b_out, N_TOKENS, D_MODEL, K2);

    layernorm<<<N_TOKENS, 256>>>(pre, ln_w, ln_b, out);
}

// round 7
// speedup vs baseline: 1.4932x; 1.4932x over previous
#include <cuda_runtime.h>
#include <cuda_fp16.h>
#include <math.h>
#include <stdint.h>

#define N_TOKENS 16384
#define D_MODEL  512
#define NQ       10
#define NL       2
#define DIM      1024
#define K1       1024   // 2*512  (fp16 2-term)
#define K2       2048   // 2*1024 (fp16 2-term)

#define BM 128
#define BN 256
#define BKB 128                    // K bytes per stage (64 fp16)
#define NSTAGES 4
#define TILE_A (BM*BKB)            // 16 KB
#define TILE_Bb (BN*BKB)           // 32 KB
#define STAGE_B (TILE_A+TILE_Bb)   // 48 KB
#define SMEM_TOTAL (NSTAGES*STAGE_B)   // 192 KB

__device__ __align__(16) float  g_Ur[DIM*DIM];
__device__ __align__(16) float  g_Ui[DIM*DIM];
__device__ __align__(16) float  g_xq[N_TOKENS*DIM];
__device__ __align__(16) float  g_pre[N_TOKENS*D_MODEL];
__device__ __align__(16) __half g_xs[N_TOKENS*K1];
__device__ __align__(16) __half g_Wins[DIM*K1];
__device__ __align__(16) __half g_psis[N_TOKENS*K2];
__device__ __align__(16) __half g_U2[2048*K2];
__device__ __align__(16) __half g_P[N_TOKENS*K2];
__device__ __align__(16) __half g_Wouts[D_MODEL*K2];

// ---------------- PTX helpers (sm_80-era only; no 'a' features) --------------
__device__ __forceinline__ uint32_t smem_u32(const void* p) {
    return (uint32_t)__cvta_generic_to_shared(p);
}
#define CP16(saddr, gaddr) \
    asm volatile("cp.async.cg.shared.global [%0], [%1], 16;" \
                 :: "r"(saddr), "l"(gaddr) : "memory")
#define CP_COMMIT() asm volatile("cp.async.commit_group;" ::: "memory")
#define CP_WAIT2()  asm volatile("cp.async.wait_group 2;" ::: "memory")

#define LDSM4(r0,r1,r2,r3,addr) \
    asm volatile("ldmatrix.sync.aligned.m8n8.x4.shared.b16 {%0,%1,%2,%3}, [%4];" \
                 : "=r"(r0), "=r"(r1), "=r"(r2), "=r"(r3) : "r"(addr))

#define MMA16816(c, a0,a1,a2,a3, b0,b1) \
    asm volatile("mma.sync.aligned.m16n8k16.row.col.f32.f16.f16.f32 " \
                 "{%0,%1,%2,%3}, {%4,%5,%6,%7}, {%8,%9}, {%0,%1,%2,%3};" \
                 : "+f"((c)[0]), "+f"((c)[1]), "+f"((c)[2]), "+f"((c)[3]) \
                 : "r"(a0), "r"(a1), "r"(a2), "r"(a3), "r"(b0), "r"(b1))

#define SW128(off) ((off) ^ (((off) >> 3) & 0x70))

// ---------------- fp16 mma GEMM (128x256 tile, 64x64 warp tile) --------------
// C[M,N] = A[M,Kp] @ B[N,Kp]^T ; A,B fp16 K-major. EPI=0: C fp32 (+bias).
// EPI=1: output cols are (re,im) pairs -> prob = re^2+im^2, split to fp16
//        hi/lo and written to P[M,K2] segments [hi|lo].
template<int EPI>
__global__ __launch_bounds__(256, 1)
void gemm_mma(const __half* __restrict__ A,
              const __half* __restrict__ B,
              float* __restrict__ C,
              __half* __restrict__ P,
              const float* __restrict__ bias,
              int M, int N, int Kp)
{
    extern __shared__ char smem[];
    const uint32_t S0 = smem_u32(smem);
    const int tid  = threadIdx.x;
    const int wid  = tid >> 5;
    const int lane = tid & 31;
    const int warp_m = (wid & 1) * 64;   // 2 warps along M
    const int warp_n = (wid >> 1) * 64;  // 4 warps along N
    const int m0 = blockIdx.y * BM;
    const int n0 = blockIdx.x * BN;
    const int nks = Kp / 64;

    const size_t ldb = (size_t)Kp * 2;
    const size_t Ab = (size_t)__cvta_generic_to_global(A) + (size_t)m0 * ldb;
    const size_t Bb = (size_t)__cvta_generic_to_global(B) + (size_t)n0 * ldb;

    const int a_row = (lane & 15);
    const int a_koff = (lane >> 4) << 4;
    const int b_row = (lane & 7) + ((lane >> 4) << 3);
    const int b_koff = ((lane >> 3) & 1) << 4;

    float c[4][8][4];
    #pragma unroll
    for (int mt = 0; mt < 4; mt++)
        #pragma unroll
        for (int nt = 0; nt < 8; nt++)
            #pragma unroll
            for (int j = 0; j < 4; j++) c[mt][nt][j] = 0.f;

    #pragma unroll
    for (int s = 0; s < NSTAGES - 1; s++) {
        const uint32_t saA = S0 + s * STAGE_B;
        const uint32_t saB = saA + TILE_A;
        const size_t ka = Ab + (size_t)s * BKB;
        const size_t kb = Bb + (size_t)s * BKB;
        #pragma unroll
        for (int i = 0; i < 12; i++) {
            int cc = tid + 256 * i;
            if (cc < 1024) {
                int r = cc >> 3, p = (cc & 7) * 16;
                CP16(saA + SW128(r*128 + p), ka + (size_t)r * ldb + p);
            } else {
                int c2 = cc - 1024;
                int r = c2 >> 3, p = (c2 & 7) * 16;
                CP16(saB + SW128(r*128 + p), kb + (size_t)r * ldb + p);
            }
        }
        CP_COMMIT();
    }

    for (int ks = 0; ks < nks; ks++) {
        CP_WAIT2();
        __syncthreads();

        int ld = ks + NSTAGES - 1;
        if (ld < nks) {
            int slot = ld % NSTAGES;
            const uint32_t pA = S0 + slot * STAGE_B;
            const uint32_t pB = pA + TILE_A;
            const size_t ka = Ab + (size_t)ld * BKB;
            const size_t kb = Bb + (size_t)ld * BKB;
            #pragma unroll
            for (int i = 0; i < 12; i++) {
                int cc = tid + 256 * i;
                if (cc < 1024) {
                    int r = cc >> 3, p = (cc & 7) * 16;
                    CP16(pA + SW128(r*128 + p), ka + (size_t)r * ldb + p);
                } else {
                    int c2 = cc - 1024;
                    int r = c2 >> 3, p = (c2 & 7) * 16;
                    CP16(pB + SW128(r*128 + p), kb + (size_t)r * ldb + p);
                }
            }
        }
        CP_COMMIT();

        const uint32_t saA = S0 + (ks % NSTAGES) * STAGE_B;
        const uint32_t saB = saA + TILE_A;
        #pragma unroll
        for (int kk = 0; kk < 4; kk++) {
            uint32_t a[4][4], b[4][4];
            #pragma unroll
            for (int mt = 0; mt < 4; mt++) {
                int r = warp_m + mt*16 + a_row;
                LDSM4(a[mt][0], a[mt][1], a[mt][2], a[mt][3],
                      saA + SW128(r*128 + kk*32 + a_koff));
            }
            #pragma unroll
            for (int nt2 = 0; nt2 < 4; nt2++) {
                int r = warp_n + nt2*16 + b_row;
                LDSM4(b[nt2][0], b[nt2][1], b[nt2][2], b[nt2][3],
                      saB + SW128(r*128 + kk*32 + b_koff));
            }
            #pragma unroll
            for (int mt = 0; mt < 4; mt++)
                #pragma unroll
                for (int nt = 0; nt < 8; nt++)
                    MMA16816(c[mt][nt],
                             a[mt][0], a[mt][1], a[mt][2], a[mt][3],
                             b[nt >> 1][(nt & 1) * 2],
                             b[nt >> 1][(nt & 1) * 2 + 1]);
        }
    }

    // ---- epilogue ----
    #pragma unroll
    for (int mt = 0; mt < 4; mt++) {
        int r0 = m0 + warp_m + mt*16 + (lane >> 2);
        #pragma unroll
        for (int nt = 0; nt < 8; nt++) {
            if (EPI == 0) {
                int nn = n0 + warp_n + nt*8 + 2*(lane & 3);
                float b0 = bias ? bias[nn] : 0.f;
                float b1 = bias ? bias[nn+1] : 0.f;
                float2 v0 = make_float2(c[mt][nt][0] + b0, c[mt][nt][1] + b1);
                float2 v1 = make_float2(c[mt][nt][2] + b0, c[mt][nt][3] + b1);
                *(float2*)(C + (size_t)r0 * N + nn) = v0;
                *(float2*)(C + (size_t)(r0+8) * N + nn) = v1;
            } else {
                int pcol = ((n0 + warp_n + nt*8) >> 1) + (lane & 3);
                float p0 = c[mt][nt][0]*c[mt][nt][0] + c[mt][nt][1]*c[mt][nt][1];
                float p1 = c[mt][nt][2]*c[mt][nt][2] + c[mt][nt][3]*c[mt][nt][3];
                __half h0 = __float2half(p0);
                __half l0 = __float2half(p0 - __half2float(h0));
                __half h1 = __float2half(p1);
                __half l1 = __float2half(p1 - __half2float(h1));
                __half* pr0 = P + (size_t)r0 * K2 + pcol;
                __half* pr1 = P + (size_t)(r0+8) * K2 + pcol;
                pr0[0] = h0; pr0[1024] = l0;
                pr1[0] = h1; pr1[1024] = l1;
            }
        }
    }
}

// ---------------- circuit unitary ---------------------------------------------
__device__ __forceinline__ float2 cmul(float2 a, float2 b) {
    return make_float2(a.x*b.x - a.y*b.y, a.x*b.y + a.y*b.x);
}
__device__ __forceinline__ float2 cadd(float2 a, float2 b) {
    return make_float2(a.x + b.x, a.y + b.y);
}

__global__ void build_unitary(const float* __restrict__ rot,
                              const float* __restrict__ ent,
                              float* __restrict__ Ur, float* __restrict__ Ui) {
    __shared__ float2 st[DIM];
    const int j = blockIdx.x;
    const int t = threadIdx.x;
    for (int i = t; i < DIM; i += 256)
        st[i] = make_float2(i == j ? 1.f : 0.f, 0.f);
    __syncthreads();
    for (int l = 0; l < NL; l++) {
        for (int q = 0; q < NQ; q++) {
            const float t1 = rot[(l*NQ + q)*3 + 0];
            const float t2 = rot[(l*NQ + q)*3 + 1];
            const float t3 = rot[(l*NQ + q)*3 + 2];
            float c1, s1; sincosf(0.5f*t1, &s1, &c1);
            float2 rx00 = {c1,0.f}, rx01 = {0.f,-s1}, rx10 = {0.f,-s1}, rx11 = {c1,0.f};
            float c2, s2; sincosf(0.5f*t2, &s2, &c2);
            float2 ry00 = {c2,0.f}, ry01 = {-s2,0.f}, ry10 = {s2,0.f}, ry11 = {c2,0.f};
            float2 a00 = cadd(cmul(ry00,rx00), cmul(ry01,rx10));
            float2 a01 = cadd(cmul(ry00,rx01), cmul(ry01,rx11));
            float2 a10 = cadd(cmul(ry10,rx00), cmul(ry11,rx10));
            float2 a11 = cadd(cmul(ry10,rx01), cmul(ry11,rx11));
            float cz, sz; sincosf(0.5f*t3, &sz, &cz);
            float2 ez0 = {cz,-sz}, ez1 = {cz,sz};
            float2 m00 = cmul(ez0,a00), m01 = cmul(ez0,a01);
            float2 m10 = cmul(ez1,a10), m11 = cmul(ez1,a11);
            const int mask = 1 << (NQ - 1 - q);
            for (int p = t; p < DIM/2; p += 256) {
                int i0 = ((p & ~(mask-1)) << 1) | (p & (mask-1));
                int i1 = i0 | mask;
                float2 v0 = st[i0], v1 = st[i1];
                st[i0] = cadd(cmul(m00,v0), cmul(m01,v1));
                st[i1] = cadd(cmul(m10,v0), cmul(m11,v1));
            }
            __syncthreads();
        }
        for (int i = t; i < DIM; i += 256) {
            float ang = 0.f;
            #pragma unroll
            for (int g = 0; g < NQ-1; g++) {
                int b1 = (i >> (NQ-1-g)) & 1;
                int b2 = (i >> (NQ-2-g)) & 1;
                if (b1 & b2) ang += ent[l*(NQ-1) + g];
            }
            float sn, cs; sincosf(ang, &sn, &cs);
            st[i] = cmul(st[i], make_float2(cs, sn));
        }
        __syncthreads();
    }
    for (int i = t; i < DIM; i += 256) {
        Ur[i*DIM + j] = st[i].x;
        Ui[i*DIM + j] = st[i].y;
    }
}

// ---------------- split / pack (fp16 2-term) -----------------------------------
__device__ __forceinline__ void split2h(float v, __half& h, __half& l) {
    h = __float2half(v);
    l = __float2half(v - __half2float(h));
}

// x [16384,512] -> xs [16384,1024] = [hx|lx]
__global__ void split_x(const float* __restrict__ x, __half* __restrict__ xs) {
    int i = blockIdx.x * blockDim.x + threadIdx.x;
    if (i >= N_TOKENS * D_MODEL) return;
    int m = i / D_MODEL, k = i % D_MODEL;
    __half h, l; split2h(x[i], h, l);
    __half* row = xs + (size_t)m * K1;
    row[k] = h; row[512 + k] = l;
}

// W_in [1024,512] -> Wins [1024,1024] = [hy|hy]
__global__ void split_Win(const float* __restrict__ W, __half* __restrict__ Ws) {
    int i = blockIdx.x * blockDim.x + threadIdx.x;
    if (i >= DIM * D_MODEL) return;
    int n = i / D_MODEL, k = i % D_MODEL;
    __half h = __float2half(W[i]);
    __half* row = Ws + (size_t)n * K1;
    row[k] = h; row[512 + k] = h;
}

// W_out [512,1024] -> Wouts [512,2048] = [hy|hy]
__global__ void split_Wout(const float* __restrict__ W, __half* __restrict__ Ws) {
    int i = blockIdx.x * blockDim.x + threadIdx.x;
    if (i >= D_MODEL * DIM) return;
    int n = i / DIM, k = i % DIM;
    __half h = __float2half(W[i]);
    __half* row = Ws + (size_t)n * K2;
    row[k] = h; row[1024 + k] = h;
}

// U2 rows: 2j = Ur[j,:], 2j+1 = Ui[j,:]; cols [hy|hy]
__global__ void pack_U(const float* __restrict__ Ur, const float* __restrict__ Ui,
                       __half* __restrict__ U2) {
    int i = blockIdx.x * blockDim.x + threadIdx.x;
    if (i >= 2048 * DIM) return;
    int n = i / DIM, k = i % DIM;
    int j = n >> 1;
    float v = (n & 1) ? Ui[(size_t)j*DIM + k] : Ur[(size_t)j*DIM + k];
    __half h = __float2half(v);
    __half* row = U2 + (size_t)n * K2;
    row[k] = h; row[1024 + k] = h;
}

// ---------------- reductions ----------------------------------------------------
__device__ float blockReduceSum256(float v) {
    __shared__ float sh[8];
    __syncthreads();
    int lane = threadIdx.x & 31, wid = threadIdx.x >> 5;
    #pragma unroll
    for (int o = 16; o > 0; o >>= 1) v += __shfl_down_sync(0xffffffffu, v, o);
    if (lane == 0) sh[wid] = v;
    __syncthreads();
    float s = 0.f;
    if (threadIdx.x < 8) s = sh[threadIdx.x];
    if (wid == 0) {
        #pragma unroll
        for (int o = 4; o > 0; o >>= 1) s += __shfl_down_sync(0xffu, s, o);
        if (lane == 0) sh[0] = s;
    }
    __syncthreads();
    return sh[0];
}

// psi = xq/||xq|| -> psis [16384,2048] = [hx|lx]
__global__ void rownorm_split(const float* __restrict__ xq,
                              __half* __restrict__ psis) {
    const int row = blockIdx.x;
    const float* p = xq + (size_t)row * DIM;
    const int t = threadIdx.x;
    float v0 = p[t], v1 = p[t+256], v2 = p[t+512], v3 = p[t+768];
    float ss = blockReduceSum256(v0*v0 + v1*v1 + v2*v2 + v3*v3);
    float sc = 1.f / fmaxf(sqrtf(ss), 1e-12f);
    __half* out = psis + (size_t)row * K2;
    float vv[4] = {v0*sc, v1*sc, v2*sc, v3*sc};
    #pragma unroll
    for (int i = 0; i < 4; i++) {
        int k = t + i*256;
        __half h, l; split2h(vv[i], h, l);
        out[k] = h; out[1024 + k] = l;
    }
}

__global__ void layernorm(const float* __restrict__ in,
                          const float* __restrict__ w, const float* __restrict__ b,
                          float* __restrict__ out) {
    const int row = blockIdx.x;
    const float* p = in + (size_t)row * D_MODEL;
    const int t = threadIdx.x;
    float v0 = p[t], v1 = p[t+256];
    float mu = blockReduceSum256(v0 + v1) * (1.f / D_MODEL);
    float d0 = v0 - mu, d1 = v1 - mu;
    float var = blockReduceSum256(d0*d0 + d1*d1) * (1.f / D_MODEL);
    float inv = rsqrtf(var + 1e-5f);
    float* o = out + (size_t)row * D_MODEL;
    o[t]     = d0 * inv * w[t]     + b[t];
    o[t+256] = d1 * inv * w[t+256] + b[t+256];
}

// ---------------- launch ---------------------------------------------------------
extern "C" void kernel_launch(void* const* d_in, const int* in_sizes, int n_in,
                              void* d_out, int out_size) {
    const float* x     = (const float*)d_in[0];
    const float* W_in  = (const float*)d_in[1];
    const float* b_in  = (const float*)d_in[2];
    const float* W_out = (const float*)d_in[3];
    const float* b_out = (const float*)d_in[4];
    const float* rot   = (const float*)d_in[5];
    const float* ent   = (const float*)d_in[6];
    const float* ln_w  = (const float*)d_in[7];
    const float* ln_b  = (const float*)d_in[8];
    float* out = (float*)d_out;

    float *Ur, *Ui, *xq, *pre;
    __half *xs, *Wins, *psis, *U2, *P, *Wouts;
    cudaGetSymbolAddress((void**)&Ur,    g_Ur);
    cudaGetSymbolAddress((void**)&Ui,    g_Ui);
    cudaGetSymbolAddress((void**)&xq,    g_xq);
    cudaGetSymbolAddress((void**)&pre,   g_pre);
    cudaGetSymbolAddress((void**)&xs,    g_xs);
    cudaGetSymbolAddress((void**)&Wins,  g_Wins);
    cudaGetSymbolAddress((void**)&psis,  g_psis);
    cudaGetSymbolAddress((void**)&U2,    g_U2);
    cudaGetSymbolAddress((void**)&P,     g_P);
    cudaGetSymbolAddress((void**)&Wouts, g_Wouts);

    cudaFuncSetAttribute(gemm_mma<0>, cudaFuncAttributeMaxDynamicSharedMemorySize, SMEM_TOTAL);
    cudaFuncSetAttribute(gemm_mma<1>, cudaFuncAttributeMaxDynamicSharedMemorySize, SMEM_TOTAL);

    build_unitary<<<DIM, 256>>>(rot, ent, Ur, Ui);
    pack_U<<<(2048*DIM + 255)/256, 256>>>(Ur, Ui, U2);
    split_x<<<(N_TOKENS*D_MODEL + 255)/256, 256>>>(x, xs);
    split_Win<<<(DIM*D_MODEL + 255)/256, 256>>>(W_in, Wins);
    split_Wout<<<(D_MODEL*DIM + 255)/256, 256>>>(W_out, Wouts);

    // GEMM1: xq = x @ fp16(W_in)^T + b_in  (K'=1024)
    gemm_mma<0><<<dim3(DIM/BN, N_TOKENS/BM), 256, SMEM_TOTAL>>>(
        xs, Wins, xq, nullptr, b_in, N_TOKENS, DIM, K1);

    // normalize + split -> psis (K'=2048)
    rownorm_split<<<N_TOKENS, 256>>>(xq, psis);

    // GEMM2: (re,im) interleaved vs U2 (N=2048); epilogue emits P = split probs
    gemm_mma<1><<<dim3(2048/BN, N_TOKENS/BM), 256, SMEM_TOTAL>>>(
        psis, U2, nullptr, P, nullptr, N_TOKENS, 2048, K2);

    // GEMM3: pre = probs @ fp16(W_out)^T + b_out
    gemm_mma<0><<<dim3(D_MODEL/BN, N_TOKENS/BM), 256, SMEM_TOTAL>>>(
        P, Wouts, pre, nullptr, b_out, N_TOKENS, D_MODEL, K2);

    layernorm<<<N_TOKENS, 256>>>(pre, ln_w, ln_b, out);
}

// round 8
// speedup vs baseline: 2.1880x; 1.4653x over previous
#include <cuda_runtime.h>
#include <cuda_fp16.h>
#include <math.h>
#include <stdint.h>

#define N_TOKENS 16384
#define D_MODEL  512
#define NQ       10
#define NL       2
#define DIM      1024
#define KA       1024   // GEMM_A: 2-term split of x (K=512)
#define K2       2048   // C-build / GEMM3: 2-term split of K=1024

#define BM 128
#define BN 256
#define BKB 128                    // K bytes per stage (64 fp16)
#define NSTAGES 4
#define TILE_A (BM*BKB)            // 16 KB
#define TILE_Bb (BN*BKB)           // 32 KB
#define STAGE_B (TILE_A+TILE_Bb)   // 48 KB
#define SMEM_TOTAL (NSTAGES*STAGE_B)   // 192 KB

__device__ __align__(16) float  g_Ur[DIM*DIM];
__device__ __align__(16) float  g_Ui[DIM*DIM];
__device__ __align__(16) __half g_Us[2048*K2];        // U_stk split [h|l]
__device__ __align__(16) __half g_WinTs[D_MODEL*K2];  // Win^T dup [h|h]
__device__ __align__(16) float  g_Cf[2048*D_MODEL];   // C = U_stk @ Win (fp32)
__device__ __align__(16) __half g_Cs[2048*KA];        // fp16(C) dup [h|h]
__device__ __align__(16) float  g_d[2048];            // U_stk @ b_in
__device__ __align__(16) __half g_xs[N_TOKENS*KA];    // x split [h|l]
__device__ __align__(16) float  g_amp[N_TOKENS*2048]; // raw (re,im) interleaved
__device__ __align__(16) __half g_P[N_TOKENS*K2];     // probs split [h|l]
__device__ __align__(16) __half g_Wouts[D_MODEL*K2];  // W_out dup [h|h]
__device__ __align__(16) float  g_pre[N_TOKENS*D_MODEL];

// ---------------- PTX helpers (sm_80-era only; no 'a' features) --------------
__device__ __forceinline__ uint32_t smem_u32(const void* p) {
    return (uint32_t)__cvta_generic_to_shared(p);
}
#define CP16(saddr, gaddr) \
    asm volatile("cp.async.cg.shared.global [%0], [%1], 16;" \
                 :: "r"(saddr), "l"(gaddr) : "memory")
#define CP_COMMIT() asm volatile("cp.async.commit_group;" ::: "memory")
#define CP_WAIT2()  asm volatile("cp.async.wait_group 2;" ::: "memory")

#define LDSM4(r0,r1,r2,r3,addr) \
    asm volatile("ldmatrix.sync.aligned.m8n8.x4.shared.b16 {%0,%1,%2,%3}, [%4];" \
                 : "=r"(r0), "=r"(r1), "=r"(r2), "=r"(r3) : "r"(addr))

#define MMA16816(c, a0,a1,a2,a3, b0,b1) \
    asm volatile("mma.sync.aligned.m16n8k16.row.col.f32.f16.f16.f32 " \
                 "{%0,%1,%2,%3}, {%4,%5,%6,%7}, {%8,%9}, {%0,%1,%2,%3};" \
                 : "+f"((c)[0]), "+f"((c)[1]), "+f"((c)[2]), "+f"((c)[3]) \
                 : "r"(a0), "r"(a1), "r"(a2), "r"(a3), "r"(b0), "r"(b1))

#define SW128(off) ((off) ^ (((off) >> 3) & 0x70))

// ---------------- fp16 mma GEMM (128x256 tile, 64x64 warp tile) --------------
// C[M,N] = A[M,Kp] @ B[N,Kp]^T + bias[n] ; A,B fp16 K-major; C fp32.
__global__ __launch_bounds__(256, 1)
void gemm_mma(const __half* __restrict__ A,
              const __half* __restrict__ B,
              float* __restrict__ C,
              const float* __restrict__ bias,
              int M, int N, int Kp)
{
    extern __shared__ char smem[];
    const uint32_t S0 = smem_u32(smem);
    const int tid  = threadIdx.x;
    const int wid  = tid >> 5;
    const int lane = tid & 31;
    const int warp_m = (wid & 1) * 64;
    const int warp_n = (wid >> 1) * 64;
    const int m0 = blockIdx.y * BM;
    const int n0 = blockIdx.x * BN;
    const int nks = Kp / 64;

    const size_t ldb = (size_t)Kp * 2;
    const size_t Ab = (size_t)__cvta_generic_to_global(A) + (size_t)m0 * ldb;
    const size_t Bb = (size_t)__cvta_generic_to_global(B) + (size_t)n0 * ldb;

    const int a_row = (lane & 15);
    const int a_koff = (lane >> 4) << 4;
    const int b_row = (lane & 7) + ((lane >> 4) << 3);
    const int b_koff = ((lane >> 3) & 1) << 4;

    float c[4][8][4];
    #pragma unroll
    for (int mt = 0; mt < 4; mt++)
        #pragma unroll
        for (int nt = 0; nt < 8; nt++)
            #pragma unroll
            for (int j = 0; j < 4; j++) c[mt][nt][j] = 0.f;

    #pragma unroll
    for (int s = 0; s < NSTAGES - 1; s++) {
        const uint32_t saA = S0 + s * STAGE_B;
        const uint32_t saB = saA + TILE_A;
        const size_t ka = Ab + (size_t)s * BKB;
        const size_t kb = Bb + (size_t)s * BKB;
        #pragma unroll
        for (int i = 0; i < 12; i++) {
            int cc = tid + 256 * i;
            if (cc < 1024) {
                int r = cc >> 3, p = (cc & 7) * 16;
                CP16(saA + SW128(r*128 + p), ka + (size_t)r * ldb + p);
            } else {
                int c2 = cc - 1024;
                int r = c2 >> 3, p = (c2 & 7) * 16;
                CP16(saB + SW128(r*128 + p), kb + (size_t)r * ldb + p);
            }
        }
        CP_COMMIT();
    }

    for (int ks = 0; ks < nks; ks++) {
        CP_WAIT2();
        __syncthreads();

        int ld = ks + NSTAGES - 1;
        if (ld < nks) {
            int slot = ld % NSTAGES;
            const uint32_t pA = S0 + slot * STAGE_B;
            const uint32_t pB = pA + TILE_A;
            const size_t ka = Ab + (size_t)ld * BKB;
            const size_t kb = Bb + (size_t)ld * BKB;
            #pragma unroll
            for (int i = 0; i < 12; i++) {
                int cc = tid + 256 * i;
                if (cc < 1024) {
                    int r = cc >> 3, p = (cc & 7) * 16;
                    CP16(pA + SW128(r*128 + p), ka + (size_t)r * ldb + p);
                } else {
                    int c2 = cc - 1024;
                    int r = c2 >> 3, p = (c2 & 7) * 16;
                    CP16(pB + SW128(r*128 + p), kb + (size_t)r * ldb + p);
                }
            }
        }
        CP_COMMIT();

        const uint32_t saA = S0 + (ks % NSTAGES) * STAGE_B;
        const uint32_t saB = saA + TILE_A;
        #pragma unroll
        for (int kk = 0; kk < 4; kk++) {
            uint32_t a[4][4], b[4][4];
            #pragma unroll
            for (int mt = 0; mt < 4; mt++) {
                int r = warp_m + mt*16 + a_row;
                LDSM4(a[mt][0], a[mt][1], a[mt][2], a[mt][3],
                      saA + SW128(r*128 + kk*32 + a_koff));
            }
            #pragma unroll
            for (int nt2 = 0; nt2 < 4; nt2++) {
                int r = warp_n + nt2*16 + b_row;
                LDSM4(b[nt2][0], b[nt2][1], b[nt2][2], b[nt2][3],
                      saB + SW128(r*128 + kk*32 + b_koff));
            }
            #pragma unroll
            for (int mt = 0; mt < 4; mt++)
                #pragma unroll
                for (int nt = 0; nt < 8; nt++)
                    MMA16816(c[mt][nt],
                             a[mt][0], a[mt][1], a[mt][2], a[mt][3],
                             b[nt >> 1][(nt & 1) * 2],
                             b[nt >> 1][(nt & 1) * 2 + 1]);
        }
    }

    #pragma unroll
    for (int mt = 0; mt < 4; mt++) {
        int r0 = m0 + warp_m + mt*16 + (lane >> 2);
        #pragma unroll
        for (int nt = 0; nt < 8; nt++) {
            int nn = n0 + warp_n + nt*8 + 2*(lane & 3);
            float b0 = bias ? bias[nn] : 0.f;
            float b1 = bias ? bias[nn+1] : 0.f;
            float2 v0 = make_float2(c[mt][nt][0] + b0, c[mt][nt][1] + b1);
            float2 v1 = make_float2(c[mt][nt][2] + b0, c[mt][nt][3] + b1);
            *(float2*)(C + (size_t)r0 * N + nn) = v0;
            *(float2*)(C + (size_t)(r0+8) * N + nn) = v1;
        }
    }
}

// ---------------- circuit unitary ---------------------------------------------
__device__ __forceinline__ float2 cmul(float2 a, float2 b) {
    return make_float2(a.x*b.x - a.y*b.y, a.x*b.y + a.y*b.x);
}
__device__ __forceinline__ float2 cadd(float2 a, float2 b) {
    return make_float2(a.x + b.x, a.y + b.y);
}

__global__ void build_unitary(const float* __restrict__ rot,
                              const float* __restrict__ ent,
                              float* __restrict__ Ur, float* __restrict__ Ui) {
    __shared__ float2 st[DIM];
    const int j = blockIdx.x;
    const int t = threadIdx.x;
    for (int i = t; i < DIM; i += 256)
        st[i] = make_float2(i == j ? 1.f : 0.f, 0.f);
    __syncthreads();
    for (int l = 0; l < NL; l++) {
        for (int q = 0; q < NQ; q++) {
            const float t1 = rot[(l*NQ + q)*3 + 0];
            const float t2 = rot[(l*NQ + q)*3 + 1];
            const float t3 = rot[(l*NQ + q)*3 + 2];
            float c1, s1; sincosf(0.5f*t1, &s1, &c1);
            float2 rx00 = {c1,0.f}, rx01 = {0.f,-s1}, rx10 = {0.f,-s1}, rx11 = {c1,0.f};
            float c2, s2; sincosf(0.5f*t2, &s2, &c2);
            float2 ry00 = {c2,0.f}, ry01 = {-s2,0.f}, ry10 = {s2,0.f}, ry11 = {c2,0.f};
            float2 a00 = cadd(cmul(ry00,rx00), cmul(ry01,rx10));
            float2 a01 = cadd(cmul(ry00,rx01), cmul(ry01,rx11));
            float2 a10 = cadd(cmul(ry10,rx00), cmul(ry11,rx10));
            float2 a11 = cadd(cmul(ry10,rx01), cmul(ry11,rx11));
            float cz, sz; sincosf(0.5f*t3, &sz, &cz);
            float2 ez0 = {cz,-sz}, ez1 = {cz,sz};
            float2 m00 = cmul(ez0,a00), m01 = cmul(ez0,a01);
            float2 m10 = cmul(ez1,a10), m11 = cmul(ez1,a11);
            const int mask = 1 << (NQ - 1 - q);
            for (int p = t; p < DIM/2; p += 256) {
                int i0 = ((p & ~(mask-1)) << 1) | (p & (mask-1));
                int i1 = i0 | mask;
                float2 v0 = st[i0], v1 = st[i1];
                st[i0] = cadd(cmul(m00,v0), cmul(m01,v1));
                st[i1] = cadd(cmul(m10,v0), cmul(m11,v1));
            }
            __syncthreads();
        }
        for (int i = t; i < DIM; i += 256) {
            float ang = 0.f;
            #pragma unroll
            for (int g = 0; g < NQ-1; g++) {
                int b1 = (i >> (NQ-1-g)) & 1;
                int b2 = (i >> (NQ-2-g)) & 1;
                if (b1 & b2) ang += ent[l*(NQ-1) + g];
            }
            float sn, cs; sincosf(ang, &sn, &cs);
            st[i] = cmul(st[i], make_float2(cs, sn));
        }
        __syncthreads();
    }
    for (int i = t; i < DIM; i += 256) {
        Ur[i*DIM + j] = st[i].x;
        Ui[i*DIM + j] = st[i].y;
    }
}

// ---------------- split / pack (fp16 2-term) -----------------------------------
__device__ __forceinline__ void split2h(float v, __half& h, __half& l) {
    h = __float2half(v);
    l = __float2half(v - __half2float(h));
}

// U_stk rows: 2j = Ur[j,:], 2j+1 = Ui[j,:]; split -> Us [2048, 2048] = [h|l]
__global__ void pack_Ustk(const float* __restrict__ Ur, const float* __restrict__ Ui,
                          __half* __restrict__ Us) {
    int i = blockIdx.x * blockDim.x + threadIdx.x;
    if (i >= 2048 * DIM) return;
    int n = i / DIM, k = i % DIM;
    int j = n >> 1;
    float v = (n & 1) ? Ui[(size_t)j*DIM + k] : Ur[(size_t)j*DIM + k];
    __half h, l; split2h(v, h, l);
    __half* row = Us + (size_t)n * K2;
    row[k] = h; row[1024 + k] = l;
}

// Win [1024,512] -> WinTs [512, 2048] = [h|h] of Win^T
__global__ void pack_WinT(const float* __restrict__ W, __half* __restrict__ Ws) {
    int i = blockIdx.x * blockDim.x + threadIdx.x;
    if (i >= D_MODEL * DIM) return;
    int m = i / DIM, k = i % DIM;
    __half h = __float2half(W[(size_t)k * D_MODEL + m]);
    __half* row = Ws + (size_t)m * K2;
    row[k] = h; row[1024 + k] = h;
}

// Cf [2048,512] -> Cs [2048, 1024] = [h|h]
__global__ void pack_Cs(const float* __restrict__ Cf, __half* __restrict__ Cs) {
    int i = blockIdx.x * blockDim.x + threadIdx.x;
    if (i >= 2048 * D_MODEL) return;
    int n = i / D_MODEL, m = i % D_MODEL;
    __half h = __float2half(Cf[i]);
    __half* row = Cs + (size_t)n * KA;
    row[m] = h; row[512 + m] = h;
}

// d[n] = sum_k U_stk[n,k] * b_in[k]  (one warp per n)
__global__ void d_vec(const float* __restrict__ Ur, const float* __restrict__ Ui,
                      const float* __restrict__ b_in, float* __restrict__ d) {
    int n = blockIdx.x * 8 + (threadIdx.x >> 5);
    int lane = threadIdx.x & 31;
    if (n >= 2048) return;
    int j = n >> 1;
    const float* row = (n & 1) ? Ui + (size_t)j*DIM : Ur + (size_t)j*DIM;
    float s = 0.f;
    for (int k = lane; k < DIM; k += 32) s += row[k] * b_in[k];
    #pragma unroll
    for (int o = 16; o > 0; o >>= 1) s += __shfl_down_sync(0xffffffffu, s, o);
    if (lane == 0) d[n] = s;
}

// x [16384,512] -> xs [16384,1024] = [h|l]
__global__ void split_x(const float* __restrict__ x, __half* __restrict__ xs) {
    int i = blockIdx.x * blockDim.x + threadIdx.x;
    if (i >= N_TOKENS * D_MODEL) return;
    int m = i / D_MODEL, k = i % D_MODEL;
    __half h, l; split2h(x[i], h, l);
    __half* row = xs + (size_t)m * KA;
    row[k] = h; row[512 + k] = l;
}

// W_out [512,1024] -> Wouts [512,2048] = [h|h]
__global__ void split_Wout(const float* __restrict__ W, __half* __restrict__ Ws) {
    int i = blockIdx.x * blockDim.x + threadIdx.x;
    if (i >= D_MODEL * DIM) return;
    int n = i / DIM, k = i % DIM;
    __half h = __float2half(W[i]);
    __half* row = Ws + (size_t)n * K2;
    row[k] = h; row[1024 + k] = h;
}

// ---------------- reductions ----------------------------------------------------
__device__ float blockReduceSum256(float v) {
    __shared__ float sh[8];
    __syncthreads();
    int lane = threadIdx.x & 31, wid = threadIdx.x >> 5;
    #pragma unroll
    for (int o = 16; o > 0; o >>= 1) v += __shfl_down_sync(0xffffffffu, v, o);
    if (lane == 0) sh[wid] = v;
    __syncthreads();
    float s = 0.f;
    if (threadIdx.x < 8) s = sh[threadIdx.x];
    if (wid == 0) {
        #pragma unroll
        for (int o = 4; o > 0; o >>= 1) s += __shfl_down_sync(0xffu, s, o);
        if (lane == 0) sh[0] = s;
    }
    __syncthreads();
    return sh[0];
}

// per row: probs_j = (re_j^2+im_j^2) / sum_j(re^2+im^2); P = [h|l] split
__global__ void probs_norm(const float* __restrict__ amp, __half* __restrict__ P) {
    const int row = blockIdx.x;
    const int t = threadIdx.x;
    const float4* a4 = (const float4*)(amp + (size_t)row * 2048);
    float4 f0 = a4[t];          // pairs 2t, 2t+1
    float4 f1 = a4[t + 256];    // pairs 2t+512, 2t+513
    float p0 = f0.x*f0.x + f0.y*f0.y;
    float p1 = f0.z*f0.z + f0.w*f0.w;
    float p2 = f1.x*f1.x + f1.y*f1.y;
    float p3 = f1.z*f1.z + f1.w*f1.w;
    float s = blockReduceSum256(p0 + p1 + p2 + p3);
    float inv = 1.f / fmaxf(s, 1e-24f);
    p0 *= inv; p1 *= inv; p2 *= inv; p3 *= inv;
    __half h0, l0, h1, l1, h2, l2, h3, l3;
    split2h(p0, h0, l0); split2h(p1, h1, l1);
    split2h(p2, h2, l2); split2h(p3, h3, l3);
    __half* prow = P + (size_t)row * K2;
    __half2 hh01; hh01.x = h0; hh01.y = h1;
    __half2 ll01; ll01.x = l0; ll01.y = l1;
    __half2 hh23; hh23.x = h2; hh23.y = h3;
    __half2 ll23; ll23.x = l2; ll23.y = l3;
    *(__half2*)(prow + 2*t)          = hh01;
    *(__half2*)(prow + 1024 + 2*t)   = ll01;
    *(__half2*)(prow + 512 + 2*t)    = hh23;
    *(__half2*)(prow + 1536 + 2*t)   = ll23;
}

__global__ void layernorm(const float* __restrict__ in,
                          const float* __restrict__ w, const float* __restrict__ b,
                          float* __restrict__ out) {
    const int row = blockIdx.x;
    const float* p = in + (size_t)row * D_MODEL;
    const int t = threadIdx.x;
    float v0 = p[t], v1 = p[t+256];
    float mu = blockReduceSum256(v0 + v1) * (1.f / D_MODEL);
    float d0 = v0 - mu, d1 = v1 - mu;
    float var = blockReduceSum256(d0*d0 + d1*d1) * (1.f / D_MODEL);
    float inv = rsqrtf(var + 1e-5f);
    float* o = out + (size_t)row * D_MODEL;
    o[t]     = d0 * inv * w[t]     + b[t];
    o[t+256] = d1 * inv * w[t+256] + b[t+256];
}

// ---------------- launch ---------------------------------------------------------
extern "C" void kernel_launch(void* const* d_in, const int* in_sizes, int n_in,
                              void* d_out, int out_size) {
    const float* x     = (const float*)d_in[0];
    const float* W_in  = (const float*)d_in[1];
    const float* b_in  = (const float*)d_in[2];
    const float* W_out = (const float*)d_in[3];
    const float* b_out = (const float*)d_in[4];
    const float* rot   = (const float*)d_in[5];
    const float* ent   = (const float*)d_in[6];
    const float* ln_w  = (const float*)d_in[7];
    const float* ln_b  = (const float*)d_in[8];
    float* out = (float*)d_out;

    float *Ur, *Ui, *Cf, *dv, *amp, *pre;
    __half *Us, *WinTs, *Cs, *xs, *P, *Wouts;
    cudaGetSymbolAddress((void**)&Ur,    g_Ur);
    cudaGetSymbolAddress((void**)&Ui,    g_Ui);
    cudaGetSymbolAddress((void**)&Us,    g_Us);
    cudaGetSymbolAddress((void**)&WinTs, g_WinTs);
    cudaGetSymbolAddress((void**)&Cf,    g_Cf);
    cudaGetSymbolAddress((void**)&Cs,    g_Cs);
    cudaGetSymbolAddress((void**)&dv,    g_d);
    cudaGetSymbolAddress((void**)&xs,    g_xs);
    cudaGetSymbolAddress((void**)&amp,   g_amp);
    cudaGetSymbolAddress((void**)&P,     g_P);
    cudaGetSymbolAddress((void**)&Wouts, g_Wouts);
    cudaGetSymbolAddress((void**)&pre,   g_pre);

    cudaFuncSetAttribute(gemm_mma, cudaFuncAttributeMaxDynamicSharedMemorySize, SMEM_TOTAL);

    // 1) circuit unitary
    build_unitary<<<DIM, 256>>>(rot, ent, Ur, Ui);

    // 2) packs for C-build
    pack_Ustk<<<(2048*DIM + 255)/256, 256>>>(Ur, Ui, Us);
    pack_WinT<<<(D_MODEL*DIM + 255)/256, 256>>>(W_in, WinTs);

    // 3) C = U_stk @ Win  [2048 x 512] fp32   (K'=2048)
    gemm_mma<<<dim3(D_MODEL/BN, 2048/BM), 256, SMEM_TOTAL>>>(
        Us, WinTs, Cf, nullptr, 2048, D_MODEL, K2);

    // 4) d = U_stk @ b_in ; pack C; split x; pack W_out
    d_vec<<<256, 256>>>(Ur, Ui, b_in, dv);
    pack_Cs<<<(2048*D_MODEL + 255)/256, 256>>>(Cf, Cs);
    split_x<<<(N_TOKENS*D_MODEL + 255)/256, 256>>>(x, xs);
    split_Wout<<<(D_MODEL*DIM + 255)/256, 256>>>(W_out, Wouts);

    // 5) amp = x @ C^T + d   [16384 x 2048] fp32  (K'=1024)
    gemm_mma<<<dim3(2048/BN, N_TOKENS/BM), 256, SMEM_TOTAL>>>(
        xs, Cs, amp, dv, N_TOKENS, 2048, KA);

    // 6) probs = |amp|^2 / rowsum(|amp|^2)  -> P [h|l]   (unitarity: rowsum == ||xq||^2)
    probs_norm<<<N_TOKENS, 256>>>(amp, P);

    // 7) pre = probs @ W_out^T + b_out  (K'=2048)
    gemm_mma<<<dim3(D_MODEL/BN, N_TOKENS/BM), 256, SMEM_TOTAL>>>(
        P, Wouts, pre, b_out, N_TOKENS, D_MODEL, K2);

    // 8) LayerNorm
    layernorm<<<N_TOKENS, 256>>>(pre, ln_w, ln_b, out);
}

// round 9
// speedup vs baseline: 3.2706x; 1.4948x over previous
#include <cuda_runtime.h>
#include <cuda_fp16.h>
#include <math.h>
#include <stdint.h>

#define N_TOKENS 16384
#define D_MODEL  512
#define NQ       10
#define NL       2
#define DIM      1024
#define K2       2048   // C-build: 2-term split of K=1024

#define BM 128
#define BN 256
#define BKB 128                    // K bytes per stage (64 fp16)
#define NSTAGES 4
#define TILE_A (BM*BKB)            // 16 KB
#define TILE_Bb (BN*BKB)           // 32 KB
#define STAGE_B (TILE_A+TILE_Bb)   // 48 KB
#define SMEM_TOTAL (NSTAGES*STAGE_B)   // 192 KB

__device__ __align__(16) float  g_Ur[DIM*DIM];
__device__ __align__(16) float  g_Ui[DIM*DIM];
__device__ __align__(16) __half g_Us[2048*K2];          // U_stk split [h|l]
__device__ __align__(16) __half g_WinTs[D_MODEL*K2];    // Win^T dup [h|h]
__device__ __align__(16) float  g_Cf[2*2048*D_MODEL];   // split-K partials
__device__ __align__(16) __half g_Cs[2048*D_MODEL];     // fp16(C) [2048,512]
__device__ __align__(16) float  g_d[2048];              // U_stk @ b_in
__device__ __align__(16) __half g_xs[N_TOKENS*D_MODEL]; // fp16(x)
__device__ __align__(16) float  g_amp[N_TOKENS*2048];   // (re,im) interleaved
__device__ __align__(16) __half g_P[N_TOKENS*DIM];      // fp16(probs)
__device__ __align__(16) __half g_Wouts[D_MODEL*DIM];   // fp16(W_out)
__device__ __align__(16) float  g_pre[N_TOKENS*D_MODEL];

// ---------------- PTX helpers (sm_80-era only; no 'a' features) --------------
__device__ __forceinline__ uint32_t smem_u32(const void* p) {
    return (uint32_t)__cvta_generic_to_shared(p);
}
#define CP16(saddr, gaddr) \
    asm volatile("cp.async.cg.shared.global [%0], [%1], 16;" \
                 :: "r"(saddr), "l"(gaddr) : "memory")
#define CP_COMMIT() asm volatile("cp.async.commit_group;" ::: "memory")
#define CP_WAIT2()  asm volatile("cp.async.wait_group 2;" ::: "memory")

#define LDSM4(r0,r1,r2,r3,addr) \
    asm volatile("ldmatrix.sync.aligned.m8n8.x4.shared.b16 {%0,%1,%2,%3}, [%4];" \
                 : "=r"(r0), "=r"(r1), "=r"(r2), "=r"(r3) : "r"(addr))

#define MMA16816(c, a0,a1,a2,a3, b0,b1) \
    asm volatile("mma.sync.aligned.m16n8k16.row.col.f32.f16.f16.f32 " \
                 "{%0,%1,%2,%3}, {%4,%5,%6,%7}, {%8,%9}, {%0,%1,%2,%3};" \
                 : "+f"((c)[0]), "+f"((c)[1]), "+f"((c)[2]), "+f"((c)[3]) \
                 : "r"(a0), "r"(a1), "r"(a2), "r"(a3), "r"(b0), "r"(b1))

#define SW128(off) ((off) ^ (((off) >> 3) & 0x70))

// ---------------- fp16 mma GEMM (128x256 tile, 64x64 warp tile) --------------
// Cz[M,N] = A[M, z*Ks : (z+1)*Ks] @ B[..]^T + bias ; z = blockIdx.z (split-K),
// partial z writes to C + z*M*N. Kfull = row stride of A,B in elements.
__global__ __launch_bounds__(256, 1)
void gemm_mma(const __half* __restrict__ A,
              const __half* __restrict__ B,
              float* __restrict__ C,
              const float* __restrict__ bias,
              int M, int N, int Ks, int Kfull)
{
    extern __shared__ char smem[];
    const uint32_t S0 = smem_u32(smem);
    const int tid  = threadIdx.x;
    const int wid  = tid >> 5;
    const int lane = tid & 31;
    const int warp_m = (wid & 1) * 64;
    const int warp_n = (wid >> 1) * 64;
    const int m0 = blockIdx.y * BM;
    const int n0 = blockIdx.x * BN;
    const int nks = Ks / 64;

    const size_t ldb = (size_t)Kfull * 2;
    const size_t koff = (size_t)blockIdx.z * Ks * 2;
    const size_t Ab = (size_t)__cvta_generic_to_global(A) + (size_t)m0 * ldb + koff;
    const size_t Bb = (size_t)__cvta_generic_to_global(B) + (size_t)n0 * ldb + koff;

    const int a_row = (lane & 15);
    const int a_koff = (lane >> 4) << 4;
    const int b_row = (lane & 7) + ((lane >> 4) << 3);
    const int b_koff = ((lane >> 3) & 1) << 4;

    float c[4][8][4];
    #pragma unroll
    for (int mt = 0; mt < 4; mt++)
        #pragma unroll
        for (int nt = 0; nt < 8; nt++)
            #pragma unroll
            for (int j = 0; j < 4; j++) c[mt][nt][j] = 0.f;

    #pragma unroll
    for (int s = 0; s < NSTAGES - 1; s++) {
        const uint32_t saA = S0 + s * STAGE_B;
        const uint32_t saB = saA + TILE_A;
        const size_t ka = Ab + (size_t)s * BKB;
        const size_t kb = Bb + (size_t)s * BKB;
        #pragma unroll
        for (int i = 0; i < 12; i++) {
            int cc = tid + 256 * i;
            if (cc < 1024) {
                int r = cc >> 3, p = (cc & 7) * 16;
                CP16(saA + SW128(r*128 + p), ka + (size_t)r * ldb + p);
            } else {
                int c2 = cc - 1024;
                int r = c2 >> 3, p = (c2 & 7) * 16;
                CP16(saB + SW128(r*128 + p), kb + (size_t)r * ldb + p);
            }
        }
        CP_COMMIT();
    }

    for (int ks = 0; ks < nks; ks++) {
        CP_WAIT2();
        __syncthreads();

        int ld = ks + NSTAGES - 1;
        if (ld < nks) {
            int slot = ld % NSTAGES;
            const uint32_t pA = S0 + slot * STAGE_B;
            const uint32_t pB = pA + TILE_A;
            const size_t ka = Ab + (size_t)ld * BKB;
            const size_t kb = Bb + (size_t)ld * BKB;
            #pragma unroll
            for (int i = 0; i < 12; i++) {
                int cc = tid + 256 * i;
                if (cc < 1024) {
                    int r = cc >> 3, p = (cc & 7) * 16;
                    CP16(pA + SW128(r*128 + p), ka + (size_t)r * ldb + p);
                } else {
                    int c2 = cc - 1024;
                    int r = c2 >> 3, p = (c2 & 7) * 16;
                    CP16(pB + SW128(r*128 + p), kb + (size_t)r * ldb + p);
                }
            }
        }
        CP_COMMIT();

        const uint32_t saA = S0 + (ks % NSTAGES) * STAGE_B;
        const uint32_t saB = saA + TILE_A;
        #pragma unroll
        for (int kk = 0; kk < 4; kk++) {
            uint32_t a[4][4], b[4][4];
            #pragma unroll
            for (int mt = 0; mt < 4; mt++) {
                int r = warp_m + mt*16 + a_row;
                LDSM4(a[mt][0], a[mt][1], a[mt][2], a[mt][3],
                      saA + SW128(r*128 + kk*32 + a_koff));
            }
            #pragma unroll
            for (int nt2 = 0; nt2 < 4; nt2++) {
                int r = warp_n + nt2*16 + b_row;
                LDSM4(b[nt2][0], b[nt2][1], b[nt2][2], b[nt2][3],
                      saB + SW128(r*128 + kk*32 + b_koff));
            }
            #pragma unroll
            for (int mt = 0; mt < 4; mt++)
                #pragma unroll
                for (int nt = 0; nt < 8; nt++)
                    MMA16816(c[mt][nt],
                             a[mt][0], a[mt][1], a[mt][2], a[mt][3],
                             b[nt >> 1][(nt & 1) * 2],
                             b[nt >> 1][(nt & 1) * 2 + 1]);
        }
    }

    float* Cz = C + (size_t)blockIdx.z * M * N;
    #pragma unroll
    for (int mt = 0; mt < 4; mt++) {
        int r0 = m0 + warp_m + mt*16 + (lane >> 2);
        #pragma unroll
        for (int nt = 0; nt < 8; nt++) {
            int nn = n0 + warp_n + nt*8 + 2*(lane & 3);
            float b0 = bias ? bias[nn] : 0.f;
            float b1 = bias ? bias[nn+1] : 0.f;
            float2 v0 = make_float2(c[mt][nt][0] + b0, c[mt][nt][1] + b1);
            float2 v1 = make_float2(c[mt][nt][2] + b0, c[mt][nt][3] + b1);
            *(float2*)(Cz + (size_t)r0 * N + nn) = v0;
            *(float2*)(Cz + (size_t)(r0+8) * N + nn) = v1;
        }
    }
}

// ---------------- circuit unitary ---------------------------------------------
__device__ __forceinline__ float2 cmul(float2 a, float2 b) {
    return make_float2(a.x*b.x - a.y*b.y, a.x*b.y + a.y*b.x);
}
__device__ __forceinline__ float2 cadd(float2 a, float2 b) {
    return make_float2(a.x + b.x, a.y + b.y);
}

__global__ void build_unitary(const float* __restrict__ rot,
                              const float* __restrict__ ent,
                              float* __restrict__ Ur, float* __restrict__ Ui) {
    __shared__ float2 st[DIM];
    const int j = blockIdx.x;
    const int t = threadIdx.x;
    for (int i = t; i < DIM; i += 256)
        st[i] = make_float2(i == j ? 1.f : 0.f, 0.f);
    __syncthreads();
    for (int l = 0; l < NL; l++) {
        for (int q = 0; q < NQ; q++) {
            const float t1 = rot[(l*NQ + q)*3 + 0];
            const float t2 = rot[(l*NQ + q)*3 + 1];
            const float t3 = rot[(l*NQ + q)*3 + 2];
            float c1, s1; sincosf(0.5f*t1, &s1, &c1);
            float2 rx00 = {c1,0.f}, rx01 = {0.f,-s1}, rx10 = {0.f,-s1}, rx11 = {c1,0.f};
            float c2, s2; sincosf(0.5f*t2, &s2, &c2);
            float2 ry00 = {c2,0.f}, ry01 = {-s2,0.f}, ry10 = {s2,0.f}, ry11 = {c2,0.f};
            float2 a00 = cadd(cmul(ry00,rx00), cmul(ry01,rx10));
            float2 a01 = cadd(cmul(ry00,rx01), cmul(ry01,rx11));
            float2 a10 = cadd(cmul(ry10,rx00), cmul(ry11,rx10));
            float2 a11 = cadd(cmul(ry10,rx01), cmul(ry11,rx11));
            float cz, sz; sincosf(0.5f*t3, &sz, &cz);
            float2 ez0 = {cz,-sz}, ez1 = {cz,sz};
            float2 m00 = cmul(ez0,a00), m01 = cmul(ez0,a01);
            float2 m10 = cmul(ez1,a10), m11 = cmul(ez1,a11);
            const int mask = 1 << (NQ - 1 - q);
            for (int p = t; p < DIM/2; p += 256) {
                int i0 = ((p & ~(mask-1)) << 1) | (p & (mask-1));
                int i1 = i0 | mask;
                float2 v0 = st[i0], v1 = st[i1];
                st[i0] = cadd(cmul(m00,v0), cmul(m01,v1));
                st[i1] = cadd(cmul(m10,v0), cmul(m11,v1));
            }
            __syncthreads();
        }
        for (int i = t; i < DIM; i += 256) {
            float ang = 0.f;
            #pragma unroll
            for (int g = 0; g < NQ-1; g++) {
                int b1 = (i >> (NQ-1-g)) & 1;
                int b2 = (i >> (NQ-2-g)) & 1;
                if (b1 & b2) ang += ent[l*(NQ-1) + g];
            }
            float sn, cs; sincosf(ang, &sn, &cs);
            st[i] = cmul(st[i], make_float2(cs, sn));
        }
        __syncthreads();
    }
    for (int i = t; i < DIM; i += 256) {
        Ur[i*DIM + j] = st[i].x;
        Ui[i*DIM + j] = st[i].y;
    }
}

// ---------------- split / pack -------------------------------------------------
__device__ __forceinline__ void split2h(float v, __half& h, __half& l) {
    h = __float2half(v);
    l = __float2half(v - __half2float(h));
}

// U_stk rows: 2j = Ur[j,:], 2j+1 = Ui[j,:]; split -> Us [2048, 2048] = [h|l]
__global__ void pack_Ustk(const float* __restrict__ Ur, const float* __restrict__ Ui,
                          __half* __restrict__ Us) {
    int i = blockIdx.x * blockDim.x + threadIdx.x;
    if (i >= 2048 * DIM) return;
    int n = i / DIM, k = i % DIM;
    int j = n >> 1;
    float v = (n & 1) ? Ui[(size_t)j*DIM + k] : Ur[(size_t)j*DIM + k];
    __half h, l; split2h(v, h, l);
    __half* row = Us + (size_t)n * K2;
    row[k] = h; row[1024 + k] = l;
}

// Win [1024,512] -> WinTs [512, 2048] = [h|h] of Win^T
__global__ void pack_WinT(const float* __restrict__ W, __half* __restrict__ Ws) {
    int i = blockIdx.x * blockDim.x + threadIdx.x;
    if (i >= D_MODEL * DIM) return;
    int m = i / DIM, k = i % DIM;
    __half h = __float2half(W[(size_t)k * D_MODEL + m]);
    __half* row = Ws + (size_t)m * K2;
    row[k] = h; row[1024 + k] = h;
}

// Cs = fp16(Cf0 + Cf1)  [2048, 512]
__global__ void pack_Cs(const float* __restrict__ Cf, __half* __restrict__ Cs) {
    int i = blockIdx.x * blockDim.x + threadIdx.x;
    if (i >= 2048 * D_MODEL) return;
    Cs[i] = __float2half(Cf[i] + Cf[2048 * D_MODEL + i]);
}

// d[n] = sum_k U_stk[n,k] * b_in[k]
__global__ void d_vec(const float* __restrict__ Ur, const float* __restrict__ Ui,
                      const float* __restrict__ b_in, float* __restrict__ d) {
    int n = blockIdx.x * 8 + (threadIdx.x >> 5);
    int lane = threadIdx.x & 31;
    if (n >= 2048) return;
    int j = n >> 1;
    const float* row = (n & 1) ? Ui + (size_t)j*DIM : Ur + (size_t)j*DIM;
    float s = 0.f;
    for (int k = lane; k < DIM; k += 32) s += row[k] * b_in[k];
    #pragma unroll
    for (int o = 16; o > 0; o >>= 1) s += __shfl_down_sync(0xffffffffu, s, o);
    if (lane == 0) d[n] = s;
}

// xs = fp16(x)  [16384, 512]
__global__ void conv_x(const float* __restrict__ x, __half* __restrict__ xs) {
    int i = blockIdx.x * blockDim.x + threadIdx.x;
    int n = N_TOKENS * D_MODEL / 4;
    if (i >= n) return;
    float4 v = ((const float4*)x)[i];
    __half2 a; a.x = __float2half(v.x); a.y = __float2half(v.y);
    __half2 b; b.x = __float2half(v.z); b.y = __float2half(v.w);
    ((__half2*)xs)[2*i] = a;
    ((__half2*)xs)[2*i + 1] = b;
}

// Wouts = fp16(W_out)  [512, 1024]
__global__ void conv_Wout(const float* __restrict__ W, __half* __restrict__ Ws) {
    int i = blockIdx.x * blockDim.x + threadIdx.x;
    int n = D_MODEL * DIM / 4;
    if (i >= n) return;
    float4 v = ((const float4*)W)[i];
    __half2 a; a.x = __float2half(v.x); a.y = __float2half(v.y);
    __half2 b; b.x = __float2half(v.z); b.y = __float2half(v.w);
    ((__half2*)Ws)[2*i] = a;
    ((__half2*)Ws)[2*i + 1] = b;
}

// ---------------- reductions ----------------------------------------------------
__device__ float blockReduceSum256(float v) {
    __shared__ float sh[8];
    __syncthreads();
    int lane = threadIdx.x & 31, wid = threadIdx.x >> 5;
    #pragma unroll
    for (int o = 16; o > 0; o >>= 1) v += __shfl_down_sync(0xffffffffu, v, o);
    if (lane == 0) sh[wid] = v;
    __syncthreads();
    float s = 0.f;
    if (threadIdx.x < 8) s = sh[threadIdx.x];
    if (wid == 0) {
        #pragma unroll
        for (int o = 4; o > 0; o >>= 1) s += __shfl_down_sync(0xffu, s, o);
        if (lane == 0) sh[0] = s;
    }
    __syncthreads();
    return sh[0];
}

// probs_j = (re_j^2+im_j^2)/rowsum -> P fp16 [16384, 1024]
__global__ void probs_norm(const float* __restrict__ amp, __half* __restrict__ P) {
    const int row = blockIdx.x;
    const int t = threadIdx.x;
    const float4* a4 = (const float4*)(amp + (size_t)row * 2048);
    float4 f0 = a4[t];          // pairs 2t, 2t+1
    float4 f1 = a4[t + 256];    // pairs 512+2t, 512+2t+1
    float p0 = f0.x*f0.x + f0.y*f0.y;
    float p1 = f0.z*f0.z + f0.w*f0.w;
    float p2 = f1.x*f1.x + f1.y*f1.y;
    float p3 = f1.z*f1.z + f1.w*f1.w;
    float s = blockReduceSum256(p0 + p1 + p2 + p3);
    float inv = 1.f / fmaxf(s, 1e-24f);
    __half2 h01; h01.x = __float2half(p0 * inv); h01.y = __float2half(p1 * inv);
    __half2 h23; h23.x = __float2half(p2 * inv); h23.y = __float2half(p3 * inv);
    __half* prow = P + (size_t)row * DIM;
    *(__half2*)(prow + 2*t)       = h01;
    *(__half2*)(prow + 512 + 2*t) = h23;
}

__global__ void layernorm(const float* __restrict__ in,
                          const float* __restrict__ w, const float* __restrict__ b,
                          float* __restrict__ out) {
    const int row = blockIdx.x;
    const float* p = in + (size_t)row * D_MODEL;
    const int t = threadIdx.x;
    float v0 = p[t], v1 = p[t+256];
    float mu = blockReduceSum256(v0 + v1) * (1.f / D_MODEL);
    float d0 = v0 - mu, d1 = v1 - mu;
    float var = blockReduceSum256(d0*d0 + d1*d1) * (1.f / D_MODEL);
    float inv = rsqrtf(var + 1e-5f);
    float* o = out + (size_t)row * D_MODEL;
    o[t]     = d0 * inv * w[t]     + b[t];
    o[t+256] = d1 * inv * w[t+256] + b[t+256];
}

// ---------------- launch ---------------------------------------------------------
extern "C" void kernel_launch(void* const* d_in, const int* in_sizes, int n_in,
                              void* d_out, int out_size) {
    const float* x     = (const float*)d_in[0];
    const float* W_in  = (const float*)d_in[1];
    const float* b_in  = (const float*)d_in[2];
    const float* W_out = (const float*)d_in[3];
    const float* b_out = (const float*)d_in[4];
    const float* rot   = (const float*)d_in[5];
    const float* ent   = (const float*)d_in[6];
    const float* ln_w  = (const float*)d_in[7];
    const float* ln_b  = (const float*)d_in[8];
    float* out = (float*)d_out;

    float *Ur, *Ui, *Cf, *dv, *amp, *pre;
    __half *Us, *WinTs, *Cs, *xs, *P, *Wouts;
    cudaGetSymbolAddress((void**)&Ur,    g_Ur);
    cudaGetSymbolAddress((void**)&Ui,    g_Ui);
    cudaGetSymbolAddress((void**)&Us,    g_Us);
    cudaGetSymbolAddress((void**)&WinTs, g_WinTs);
    cudaGetSymbolAddress((void**)&Cf,    g_Cf);
    cudaGetSymbolAddress((void**)&Cs,    g_Cs);
    cudaGetSymbolAddress((void**)&dv,    g_d);
    cudaGetSymbolAddress((void**)&xs,    g_xs);
    cudaGetSymbolAddress((void**)&amp,   g_amp);
    cudaGetSymbolAddress((void**)&P,     g_P);
    cudaGetSymbolAddress((void**)&Wouts, g_Wouts);
    cudaGetSymbolAddress((void**)&pre,   g_pre);

    cudaFuncSetAttribute(gemm_mma, cudaFuncAttributeMaxDynamicSharedMemorySize, SMEM_TOTAL);

    // 1) circuit unitary
    build_unitary<<<DIM, 256>>>(rot, ent, Ur, Ui);

    // 2) packs for C-build (exact 2-term: A = [h|l] of U, B = [h|h] of Win^T)
    pack_Ustk<<<(2048*DIM + 255)/256, 256>>>(Ur, Ui, Us);
    pack_WinT<<<(D_MODEL*DIM + 255)/256, 256>>>(W_in, WinTs);

    // 3) C = U_stk @ Win [2048 x 512], split-K z=2 (K'=2048, 1024 per slice)
    gemm_mma<<<dim3(D_MODEL/BN, 2048/BM, 2), 256, SMEM_TOTAL>>>(
        Us, WinTs, Cf, nullptr, 2048, D_MODEL, 1024, K2);

    // 4) d = U_stk @ b_in ; Cs = fp16(Cf0+Cf1); xs = fp16(x); Wouts = fp16(W_out)
    d_vec<<<256, 256>>>(Ur, Ui, b_in, dv);
    pack_Cs<<<(2048*D_MODEL + 255)/256, 256>>>(Cf, Cs);
    conv_x<<<(N_TOKENS*D_MODEL/4 + 255)/256, 256>>>(x, xs);
    conv_Wout<<<(D_MODEL*DIM/4 + 255)/256, 256>>>(W_out, Wouts);

    // 5) amp = fp16(x) @ fp16(C)^T + d   [16384 x 2048], K=512
    gemm_mma<<<dim3(2048/BN, N_TOKENS/BM, 1), 256, SMEM_TOTAL>>>(
        xs, Cs, amp, dv, N_TOKENS, 2048, D_MODEL, D_MODEL);

    // 6) probs = |amp|^2 / rowsum  (unitarity gives the norm for free)
    probs_norm<<<N_TOKENS, 256>>>(amp, P);

    // 7) pre = fp16(probs) @ fp16(W_out)^T + b_out   [16384 x 512], K=1024
    gemm_mma<<<dim3(D_MODEL/BN, N_TOKENS/BM, 1), 256, SMEM_TOTAL>>>(
        P, Wouts, pre, b_out, N_TOKENS, D_MODEL, DIM, DIM);

    // 8) LayerNorm
    layernorm<<<N_TOKENS, 256>>>(pre, ln_w, ln_b, out);
}

// round 10
// speedup vs baseline: 3.5594x; 1.0883x over previous
#include <cuda_runtime.h>
#include <cuda_fp16.h>
#include <math.h>
#include <stdint.h>

#define N_TOKENS 16384
#define D_MODEL  512
#define NQ       10
#define NL       2
#define DIM      1024
#define K2       2048   // C-build: 2-term split of K=1024

#define BM 128
#define BN 256
#define BKB 128                    // K bytes per stage (64 fp16)
#define NSTAGES 4
#define TILE_A (BM*BKB)            // 16 KB
#define TILE_Bb (BN*BKB)           // 32 KB
#define STAGE_B (TILE_A+TILE_Bb)   // 48 KB
#define SMEM_TOTAL (NSTAGES*STAGE_B)   // 192 KB
#define NSPLIT 4                   // C-build split-K

__device__ __align__(16) float  g_Ur[DIM*DIM];
__device__ __align__(16) float  g_Ui[DIM*DIM];
__device__ __align__(16) __half g_Us[2048*K2];          // U_stk split [h|l]
__device__ __align__(16) __half g_WinTs[D_MODEL*K2];    // Win^T dup [h|h]
__device__ __align__(16) float  g_Cf[NSPLIT*2048*D_MODEL]; // split-K partials
__device__ __align__(16) __half g_Cs[2048*D_MODEL];     // fp16(C) [2048,512]
__device__ __align__(16) float  g_d[2048];              // U_stk @ b_in
__device__ __align__(16) __half g_xs[N_TOKENS*D_MODEL]; // fp16(x)
__device__ __align__(16) __half g_Q[N_TOKENS*DIM];      // fp16(|amp|^2) unnormalized
__device__ __align__(16) float  g_S[8*N_TOKENS];        // per-row partial sums
__device__ __align__(16) __half g_Wouts[D_MODEL*DIM];   // fp16(W_out)
__device__ __align__(16) float  g_pre[N_TOKENS*D_MODEL];

// ---------------- PTX helpers (sm_80-era only; no 'a' features) --------------
__device__ __forceinline__ uint32_t smem_u32(const void* p) {
    return (uint32_t)__cvta_generic_to_shared(p);
}
#define CP16(saddr, gaddr) \
    asm volatile("cp.async.cg.shared.global [%0], [%1], 16;" \
                 :: "r"(saddr), "l"(gaddr) : "memory")
#define CP_COMMIT() asm volatile("cp.async.commit_group;" ::: "memory")
#define CP_WAIT2()  asm volatile("cp.async.wait_group 2;" ::: "memory")

#define LDSM4(r0,r1,r2,r3,addr) \
    asm volatile("ldmatrix.sync.aligned.m8n8.x4.shared.b16 {%0,%1,%2,%3}, [%4];" \
                 : "=r"(r0), "=r"(r1), "=r"(r2), "=r"(r3) : "r"(addr))

#define MMA16816(c, a0,a1,a2,a3, b0,b1) \
    asm volatile("mma.sync.aligned.m16n8k16.row.col.f32.f16.f16.f32 " \
                 "{%0,%1,%2,%3}, {%4,%5,%6,%7}, {%8,%9}, {%0,%1,%2,%3};" \
                 : "+f"((c)[0]), "+f"((c)[1]), "+f"((c)[2]), "+f"((c)[3]) \
                 : "r"(a0), "r"(a1), "r"(a2), "r"(a3), "r"(b0), "r"(b1))

#define SW128(off) ((off) ^ (((off) >> 3) & 0x70))

// ---------------- fp16 mma GEMM (128x256 tile, 64x64 warp tile) --------------
// EPI=0: C[M,N] = A @ B^T + bias (fp32), split-K partial z -> C + z*M*N.
// EPI=1: cols are (re,im) pairs; q = (re+d)^2+(im+d')^2 -> Q fp16 [M, N/2];
//        deterministic per-row partial sums -> Spart[blockIdx.x*M + row].
template<int EPI>
__global__ __launch_bounds__(256, 1)
void gemm_mma(const __half* __restrict__ A,
              const __half* __restrict__ B,
              float* __restrict__ C,
              __half* __restrict__ Q,
              float* __restrict__ Spart,
              const float* __restrict__ bias,
              int M, int N, int Ks, int Kfull)
{
    extern __shared__ char smem[];
    __shared__ float s_w[4][BM];
    const uint32_t S0 = smem_u32(smem);
    const int tid  = threadIdx.x;
    const int wid  = tid >> 5;
    const int lane = tid & 31;
    const int warp_m = (wid & 1) * 64;
    const int warp_n = (wid >> 1) * 64;
    const int m0 = blockIdx.y * BM;
    const int n0 = blockIdx.x * BN;
    const int nks = Ks / 64;

    const size_t ldb = (size_t)Kfull * 2;
    const size_t koff = (size_t)blockIdx.z * Ks * 2;
    const size_t Ab = (size_t)__cvta_generic_to_global(A) + (size_t)m0 * ldb + koff;
    const size_t Bb = (size_t)__cvta_generic_to_global(B) + (size_t)n0 * ldb + koff;

    const int a_row = (lane & 15);
    const int a_koff = (lane >> 4) << 4;
    const int b_row = (lane & 7) + ((lane >> 4) << 3);
    const int b_koff = ((lane >> 3) & 1) << 4;

    float c[4][8][4];
    #pragma unroll
    for (int mt = 0; mt < 4; mt++)
        #pragma unroll
        for (int nt = 0; nt < 8; nt++)
            #pragma unroll
            for (int j = 0; j < 4; j++) c[mt][nt][j] = 0.f;

    #pragma unroll
    for (int s = 0; s < NSTAGES - 1; s++) {
        const uint32_t saA = S0 + s * STAGE_B;
        const uint32_t saB = saA + TILE_A;
        const size_t ka = Ab + (size_t)s * BKB;
        const size_t kb = Bb + (size_t)s * BKB;
        #pragma unroll
        for (int i = 0; i < 12; i++) {
            int cc = tid + 256 * i;
            if (cc < 1024) {
                int r = cc >> 3, p = (cc & 7) * 16;
                CP16(saA + SW128(r*128 + p), ka + (size_t)r * ldb + p);
            } else {
                int c2 = cc - 1024;
                int r = c2 >> 3, p = (c2 & 7) * 16;
                CP16(saB + SW128(r*128 + p), kb + (size_t)r * ldb + p);
            }
        }
        CP_COMMIT();
    }

    for (int ks = 0; ks < nks; ks++) {
        CP_WAIT2();
        __syncthreads();

        int ld = ks + NSTAGES - 1;
        if (ld < nks) {
            int slot = ld % NSTAGES;
            const uint32_t pA = S0 + slot * STAGE_B;
            const uint32_t pB = pA + TILE_A;
            const size_t ka = Ab + (size_t)ld * BKB;
            const size_t kb = Bb + (size_t)ld * BKB;
            #pragma unroll
            for (int i = 0; i < 12; i++) {
                int cc = tid + 256 * i;
                if (cc < 1024) {
                    int r = cc >> 3, p = (cc & 7) * 16;
                    CP16(pA + SW128(r*128 + p), ka + (size_t)r * ldb + p);
                } else {
                    int c2 = cc - 1024;
                    int r = c2 >> 3, p = (c2 & 7) * 16;
                    CP16(pB + SW128(r*128 + p), kb + (size_t)r * ldb + p);
                }
            }
        }
        CP_COMMIT();

        const uint32_t saA = S0 + (ks % NSTAGES) * STAGE_B;
        const uint32_t saB = saA + TILE_A;
        #pragma unroll
        for (int kk = 0; kk < 4; kk++) {
            uint32_t a[4][4], b[4][4];
            #pragma unroll
            for (int mt = 0; mt < 4; mt++) {
                int r = warp_m + mt*16 + a_row;
                LDSM4(a[mt][0], a[mt][1], a[mt][2], a[mt][3],
                      saA + SW128(r*128 + kk*32 + a_koff));
            }
            #pragma unroll
            for (int nt2 = 0; nt2 < 4; nt2++) {
                int r = warp_n + nt2*16 + b_row;
                LDSM4(b[nt2][0], b[nt2][1], b[nt2][2], b[nt2][3],
                      saB + SW128(r*128 + kk*32 + b_koff));
            }
            #pragma unroll
            for (int mt = 0; mt < 4; mt++)
                #pragma unroll
                for (int nt = 0; nt < 8; nt++)
                    MMA16816(c[mt][nt],
                             a[mt][0], a[mt][1], a[mt][2], a[mt][3],
                             b[nt >> 1][(nt & 1) * 2],
                             b[nt >> 1][(nt & 1) * 2 + 1]);
        }
    }

    if (EPI == 0) {
        float* Cz = C + (size_t)blockIdx.z * M * N;
        #pragma unroll
        for (int mt = 0; mt < 4; mt++) {
            int r0 = m0 + warp_m + mt*16 + (lane >> 2);
            #pragma unroll
            for (int nt = 0; nt < 8; nt++) {
                int nn = n0 + warp_n + nt*8 + 2*(lane & 3);
                float b0 = bias ? bias[nn] : 0.f;
                float b1 = bias ? bias[nn+1] : 0.f;
                float2 v0 = make_float2(c[mt][nt][0] + b0, c[mt][nt][1] + b1);
                float2 v1 = make_float2(c[mt][nt][2] + b0, c[mt][nt][3] + b1);
                *(float2*)(Cz + (size_t)r0 * N + nn) = v0;
                *(float2*)(Cz + (size_t)(r0+8) * N + nn) = v1;
            }
        }
    } else {
        const int Nq = N >> 1;
        #pragma unroll
        for (int mt = 0; mt < 4; mt++) {
            int rl0 = warp_m + mt*16 + (lane >> 2);   // local row
            float sum0 = 0.f, sum1 = 0.f;
            #pragma unroll
            for (int nt = 0; nt < 8; nt++) {
                int nn = n0 + warp_n + nt*8 + 2*(lane & 3);
                float dr = bias[nn], di = bias[nn+1];
                float re0 = c[mt][nt][0] + dr, im0 = c[mt][nt][1] + di;
                float re1 = c[mt][nt][2] + dr, im1 = c[mt][nt][3] + di;
                float q0 = re0*re0 + im0*im0;
                float q1 = re1*re1 + im1*im1;
                int pcol = (nn >> 1);
                Q[(size_t)(m0 + rl0) * Nq + pcol]     = __float2half(q0);
                Q[(size_t)(m0 + rl0 + 8) * Nq + pcol] = __float2half(q1);
                sum0 += q0; sum1 += q1;
            }
            // deterministic 4-lane reduction (lanes 4k..4k+3 share the row)
            sum0 += __shfl_down_sync(0xffffffffu, sum0, 2);
            sum0 += __shfl_down_sync(0xffffffffu, sum0, 1);
            sum1 += __shfl_down_sync(0xffffffffu, sum1, 2);
            sum1 += __shfl_down_sync(0xffffffffu, sum1, 1);
            if ((lane & 3) == 0) {
                s_w[wid >> 1][rl0]     = sum0;
                s_w[wid >> 1][rl0 + 8] = sum1;
            }
        }
        __syncthreads();
        if (tid < BM) {
            Spart[(size_t)blockIdx.x * M + m0 + tid] =
                s_w[0][tid] + s_w[1][tid] + s_w[2][tid] + s_w[3][tid];
        }
    }
}

// ---------------- circuit unitary ---------------------------------------------
__device__ __forceinline__ float2 cmul(float2 a, float2 b) {
    return make_float2(a.x*b.x - a.y*b.y, a.x*b.y + a.y*b.x);
}
__device__ __forceinline__ float2 cadd(float2 a, float2 b) {
    return make_float2(a.x + b.x, a.y + b.y);
}

__global__ void build_unitary(const float* __restrict__ rot,
                              const float* __restrict__ ent,
                              float* __restrict__ Ur, float* __restrict__ Ui) {
    __shared__ float2 st[DIM];
    const int j = blockIdx.x;
    const int t = threadIdx.x;
    for (int i = t; i < DIM; i += 256)
        st[i] = make_float2(i == j ? 1.f : 0.f, 0.f);
    __syncthreads();
    for (int l = 0; l < NL; l++) {
        for (int q = 0; q < NQ; q++) {
            const float t1 = rot[(l*NQ + q)*3 + 0];
            const float t2 = rot[(l*NQ + q)*3 + 1];
            const float t3 = rot[(l*NQ + q)*3 + 2];
            float c1, s1; sincosf(0.5f*t1, &s1, &c1);
            float2 rx00 = {c1,0.f}, rx01 = {0.f,-s1}, rx10 = {0.f,-s1}, rx11 = {c1,0.f};
            float c2, s2; sincosf(0.5f*t2, &s2, &c2);
            float2 ry00 = {c2,0.f}, ry01 = {-s2,0.f}, ry10 = {s2,0.f}, ry11 = {c2,0.f};
            float2 a00 = cadd(cmul(ry00,rx00), cmul(ry01,rx10));
            float2 a01 = cadd(cmul(ry00,rx01), cmul(ry01,rx11));
            float2 a10 = cadd(cmul(ry10,rx00), cmul(ry11,rx10));
            float2 a11 = cadd(cmul(ry10,rx01), cmul(ry11,rx11));
            float cz, sz; sincosf(0.5f*t3, &sz, &cz);
            float2 ez0 = {cz,-sz}, ez1 = {cz,sz};
            float2 m00 = cmul(ez0,a00), m01 = cmul(ez0,a01);
            float2 m10 = cmul(ez1,a10), m11 = cmul(ez1,a11);
            const int mask = 1 << (NQ - 1 - q);
            for (int p = t; p < DIM/2; p += 256) {
                int i0 = ((p & ~(mask-1)) << 1) | (p & (mask-1));
                int i1 = i0 | mask;
                float2 v0 = st[i0], v1 = st[i1];
                st[i0] = cadd(cmul(m00,v0), cmul(m01,v1));
                st[i1] = cadd(cmul(m10,v0), cmul(m11,v1));
            }
            __syncthreads();
        }
        for (int i = t; i < DIM; i += 256) {
            float ang = 0.f;
            #pragma unroll
            for (int g = 0; g < NQ-1; g++) {
                int b1 = (i >> (NQ-1-g)) & 1;
                int b2 = (i >> (NQ-2-g)) & 1;
                if (b1 & b2) ang += ent[l*(NQ-1) + g];
            }
            float sn, cs; sincosf(ang, &sn, &cs);
            st[i] = cmul(st[i], make_float2(cs, sn));
        }
        __syncthreads();
    }
    for (int i = t; i < DIM; i += 256) {
        Ur[i*DIM + j] = st[i].x;
        Ui[i*DIM + j] = st[i].y;
    }
}

// ---------------- split / pack -------------------------------------------------
__device__ __forceinline__ void split2h(float v, __half& h, __half& l) {
    h = __float2half(v);
    l = __float2half(v - __half2float(h));
}

__global__ void pack_Ustk(const float* __restrict__ Ur, const float* __restrict__ Ui,
                          __half* __restrict__ Us) {
    int i = blockIdx.x * blockDim.x + threadIdx.x;
    if (i >= 2048 * DIM) return;
    int n = i / DIM, k = i % DIM;
    int j = n >> 1;
    float v = (n & 1) ? Ui[(size_t)j*DIM + k] : Ur[(size_t)j*DIM + k];
    __half h, l; split2h(v, h, l);
    __half* row = Us + (size_t)n * K2;
    row[k] = h; row[1024 + k] = l;
}

__global__ void pack_WinT(const float* __restrict__ W, __half* __restrict__ Ws) {
    int i = blockIdx.x * blockDim.x + threadIdx.x;
    if (i >= D_MODEL * DIM) return;
    int m = i / DIM, k = i % DIM;
    __half h = __float2half(W[(size_t)k * D_MODEL + m]);
    __half* row = Ws + (size_t)m * K2;
    row[k] = h; row[1024 + k] = h;
}

// Cs = fp16(sum of NSPLIT partials)
__global__ void pack_Cs(const float* __restrict__ Cf, __half* __restrict__ Cs) {
    int i = blockIdx.x * blockDim.x + threadIdx.x;
    if (i >= 2048 * D_MODEL) return;
    float s = 0.f;
    #pragma unroll
    for (int z = 0; z < NSPLIT; z++) s += Cf[(size_t)z * 2048 * D_MODEL + i];
    Cs[i] = __float2half(s);
}

__global__ void d_vec(const float* __restrict__ Ur, const float* __restrict__ Ui,
                      const float* __restrict__ b_in, float* __restrict__ d) {
    int n = blockIdx.x * 8 + (threadIdx.x >> 5);
    int lane = threadIdx.x & 31;
    if (n >= 2048) return;
    int j = n >> 1;
    const float* row = (n & 1) ? Ui + (size_t)j*DIM : Ur + (size_t)j*DIM;
    float s = 0.f;
    for (int k = lane; k < DIM; k += 32) s += row[k] * b_in[k];
    #pragma unroll
    for (int o = 16; o > 0; o >>= 1) s += __shfl_down_sync(0xffffffffu, s, o);
    if (lane == 0) d[n] = s;
}

__global__ void conv_x(const float* __restrict__ x, __half* __restrict__ xs) {
    int i = blockIdx.x * blockDim.x + threadIdx.x;
    int n = N_TOKENS * D_MODEL / 4;
    if (i >= n) return;
    float4 v = ((const float4*)x)[i];
    __half2 a; a.x = __float2half(v.x); a.y = __float2half(v.y);
    __half2 b; b.x = __float2half(v.z); b.y = __float2half(v.w);
    ((__half2*)xs)[2*i] = a;
    ((__half2*)xs)[2*i + 1] = b;
}

__global__ void conv_Wout(const float* __restrict__ W, __half* __restrict__ Ws) {
    int i = blockIdx.x * blockDim.x + threadIdx.x;
    int n = D_MODEL * DIM / 4;
    if (i >= n) return;
    float4 v = ((const float4*)W)[i];
    __half2 a; a.x = __float2half(v.x); a.y = __float2half(v.y);
    __half2 b; b.x = __float2half(v.z); b.y = __float2half(v.w);
    ((__half2*)Ws)[2*i] = a;
    ((__half2*)Ws)[2*i + 1] = b;
}

// ---------------- reductions ----------------------------------------------------
__device__ float blockReduceSum256(float v) {
    __shared__ float sh[8];
    __syncthreads();
    int lane = threadIdx.x & 31, wid = threadIdx.x >> 5;
    #pragma unroll
    for (int o = 16; o > 0; o >>= 1) v += __shfl_down_sync(0xffffffffu, v, o);
    if (lane == 0) sh[wid] = v;
    __syncthreads();
    float s = 0.f;
    if (threadIdx.x < 8) s = sh[threadIdx.x];
    if (wid == 0) {
        #pragma unroll
        for (int o = 4; o > 0; o >>= 1) s += __shfl_down_sync(0xffu, s, o);
        if (lane == 0) sh[0] = s;
    }
    __syncthreads();
    return sh[0];
}

// pre = preU/s + b_out, then LayerNorm -> out
__global__ void finalize(const float* __restrict__ preU,
                         const float* __restrict__ Spart,
                         const float* __restrict__ b_out,
                         const float* __restrict__ w, const float* __restrict__ b,
                         float* __restrict__ out) {
    const int row = blockIdx.x;
    const int t = threadIdx.x;
    float s = 0.f;
    #pragma unroll
    for (int c = 0; c < 8; c++) s += Spart[(size_t)c * N_TOKENS + row];
    float inv_s = 1.f / fmaxf(s, 1e-24f);
    const float* p = preU + (size_t)row * D_MODEL;
    float v0 = p[t] * inv_s + b_out[t];
    float v1 = p[t+256] * inv_s + b_out[t+256];
    float mu = blockReduceSum256(v0 + v1) * (1.f / D_MODEL);
    float d0 = v0 - mu, d1 = v1 - mu;
    float var = blockReduceSum256(d0*d0 + d1*d1) * (1.f / D_MODEL);
    float inv = rsqrtf(var + 1e-5f);
    float* o = out + (size_t)row * D_MODEL;
    o[t]     = d0 * inv * w[t]     + b[t];
    o[t+256] = d1 * inv * w[t+256] + b[t+256];
}

// ---------------- launch ---------------------------------------------------------
extern "C" void kernel_launch(void* const* d_in, const int* in_sizes, int n_in,
                              void* d_out, int out_size) {
    const float* x     = (const float*)d_in[0];
    const float* W_in  = (const float*)d_in[1];
    const float* b_in  = (const float*)d_in[2];
    const float* W_out = (const float*)d_in[3];
    const float* b_out = (const float*)d_in[4];
    const float* rot   = (const float*)d_in[5];
    const float* ent   = (const float*)d_in[6];
    const float* ln_w  = (const float*)d_in[7];
    const float* ln_b  = (const float*)d_in[8];
    float* out = (float*)d_out;

    float *Ur, *Ui, *Cf, *dv, *Sp, *pre;
    __half *Us, *WinTs, *Cs, *xs, *Q, *Wouts;
    cudaGetSymbolAddress((void**)&Ur,    g_Ur);
    cudaGetSymbolAddress((void**)&Ui,    g_Ui);
    cudaGetSymbolAddress((void**)&Us,    g_Us);
    cudaGetSymbolAddress((void**)&WinTs, g_WinTs);
    cudaGetSymbolAddress((void**)&Cf,    g_Cf);
    cudaGetSymbolAddress((void**)&Cs,    g_Cs);
    cudaGetSymbolAddress((void**)&dv,    g_d);
    cudaGetSymbolAddress((void**)&xs,    g_xs);
    cudaGetSymbolAddress((void**)&Q,     g_Q);
    cudaGetSymbolAddress((void**)&Sp,    g_S);
    cudaGetSymbolAddress((void**)&Wouts, g_Wouts);
    cudaGetSymbolAddress((void**)&pre,   g_pre);

    cudaFuncSetAttribute(gemm_mma<0>, cudaFuncAttributeMaxDynamicSharedMemorySize, SMEM_TOTAL);
    cudaFuncSetAttribute(gemm_mma<1>, cudaFuncAttributeMaxDynamicSharedMemorySize, SMEM_TOTAL);

    // 1) circuit unitary
    build_unitary<<<DIM, 256>>>(rot, ent, Ur, Ui);

    // 2) packs for C-build (exact 2-term split of U; [h|h] of Win^T)
    pack_Ustk<<<(2048*DIM + 255)/256, 256>>>(Ur, Ui, Us);
    pack_WinT<<<(D_MODEL*DIM + 255)/256, 256>>>(W_in, WinTs);

    // 3) C = U_stk @ Win [2048 x 512], split-K z=4 (Ks=512 each)
    gemm_mma<0><<<dim3(D_MODEL/BN, 2048/BM, NSPLIT), 256, SMEM_TOTAL>>>(
        Us, WinTs, Cf, nullptr, nullptr, nullptr, 2048, D_MODEL, K2/NSPLIT, K2);

    // 4) d = U_stk @ b_in ; Cs = fp16(sum Cf); xs = fp16(x); Wouts = fp16(W_out)
    d_vec<<<256, 256>>>(Ur, Ui, b_in, dv);
    pack_Cs<<<(2048*D_MODEL + 255)/256, 256>>>(Cf, Cs);
    conv_x<<<(N_TOKENS*D_MODEL/4 + 255)/256, 256>>>(x, xs);
    conv_Wout<<<(D_MODEL*DIM/4 + 255)/256, 256>>>(W_out, Wouts);

    // 5) amp GEMM + fused |amp|^2 epilogue: Q fp16 [16384,1024] + row partials
    gemm_mma<1><<<dim3(2048/BN, N_TOKENS/BM, 1), 256, SMEM_TOTAL>>>(
        xs, Cs, nullptr, Q, Sp, dv, N_TOKENS, 2048, D_MODEL, D_MODEL);

    // 6) preU = Q @ fp16(W_out)^T (unnormalized, no bias)
    gemm_mma<0><<<dim3(D_MODEL/BN, N_TOKENS/BM, 1), 256, SMEM_TOTAL>>>(
        Q, Wouts, pre, nullptr, nullptr, nullptr, N_TOKENS, D_MODEL, DIM, DIM);

    // 7) finalize: pre/s + b_out, LayerNorm
    finalize<<<N_TOKENS, 256>>>(pre, Sp, b_out, ln_w, ln_b, out);
}